// round 14
// baseline (speedup 1.0000x reference)
#include <cuda_runtime.h>
#include <cuda_fp16.h>
#include <cstdint>

// B=8, C=64, T=128
#define HW_   16384
#define CHW_  1048576
#define GBS_  3145728

typedef unsigned long long ull;

// ---------------- scratch ----------------
__device__ float d_t  [12582912];  // half [8,192,128,128] conv1x1 out
__device__ float d_g  [12582912];  // half [8,192,128,128] gates (planar)
__device__ float d_xt1[8388608];   // half2 [b][h/2][c][w]
__device__ float d_xt2[8388608];   // half2 [b][w/2][h][c]
__device__ float d_xr [8388608];   // half2 [b][c/2][h][w]
__device__ float d_xhw[4194304];   // half planar [b][c][h][w]
__device__ float d_xcw[4194304];
__device__ float d_xhc[4194304];
__device__ float d_mid[8388608];   // half2 [b][c/2][h][w]
__device__ float d_o1 [8388608];   // half2 [b][c/2][h][w]
__device__ float d_wr [405504];    // fp16 conv weights (lane-fragment order)
__device__ float d_w1 [12288];     // fp16 1x1 weights
__device__ float d_wdf[8192];      // fp16 down-GEMM weights

__device__ __forceinline__ float lrelu(float v) { return v > 0.f ? v : 0.1f * v; }

__device__ __forceinline__ void cp_async16(uint32_t dst, const void* src, bool valid) {
    int sz = valid ? 16 : 0;
    asm volatile("cp.async.cg.shared.global [%0], [%1], 16, %2;\n"
                 :: "r"(dst), "l"(src), "r"(sz));
}
__device__ __forceinline__ void cp_commit() { asm volatile("cp.async.commit_group;\n"); }
__device__ __forceinline__ void cp_wait0()  { asm volatile("cp.async.wait_group 0;\n"); }

__device__ __forceinline__ float4 h4_to_f4(uint2 u) {
    float2 a = __half22float2(*(__half2*)&u.x);
    float2 b = __half22float2(*(__half2*)&u.y);
    return make_float4(a.x, a.y, b.x, b.y);
}

// ---------------- fp16 mma (m16n8k16, fp32 accum) ----------------
__device__ __forceinline__ void mma_f16(float* d, const uint32_t* a,
                                        uint32_t b0, uint32_t b1) {
    asm volatile("mma.sync.aligned.m16n8k16.row.col.f32.f16.f16.f32 "
                 "{%0,%1,%2,%3}, {%4,%5,%6,%7}, {%8,%9}, {%0,%1,%2,%3};"
                 : "+f"(d[0]), "+f"(d[1]), "+f"(d[2]), "+f"(d[3])
                 : "r"(a[0]), "r"(a[1]), "r"(a[2]), "r"(a[3]), "r"(b0), "r"(b1));
}

// ---------------- prep device helpers ----------------
__device__ __forceinline__ void prep_wf_one(const float* __restrict__ src,
                                            __half* __restrict__ dst,
                                            int C, int idx, int PERM)
{
    int klo  = idx & 1;
    int q    = (idx >> 1) & 3;
    int lane = (idx >> 3) & 31;
    int mt   = (idx >> 8) & 3;
    int s    = (idx >> 10) % 9;
    int rest = idx / 9216;
    int NS = C >> 4;
    int slab = rest % NS;
    int ocb = rest / NS;
    int g = lane >> 2, tq = lane & 3;
    int oc_l = 16 * mt + 8 * (q & 1) + g;
    if (PERM) {
        int grp = oc_l >> 4, r = oc_l & 15;
        oc_l = grp * 16 + ((r < 8) ? 2 * r : 2 * (r - 8) + 1);
    }
    int k = slab * 16 + 2 * (tq + 4 * (q >> 1)) + klo;
    dst[idx] = __float2half_rn(src[((ocb * 64 + oc_l) * C + k) * 9 + s]);
}

__device__ __forceinline__ void prep_w1_one(const float* __restrict__ src,
                                            __half* __restrict__ dst, int idx)
{
    int klo  = idx & 1;
    int q    = (idx >> 1) & 3;
    int lane = (idx >> 3) & 31;
    int mt   = (idx >> 8) & 3;
    int slab = (idx >> 10) & 3;
    int ocb  = idx >> 12;
    int g = lane >> 2, tq = lane & 3;
    int oc_l = 16 * mt + 8 * (q & 1) + g;
    int k = slab * 16 + 2 * (tq + 4 * (q >> 1)) + klo;
    dst[idx] = __float2half_rn(src[(ocb * 64 + oc_l) * 64 + k]);
}

__device__ __forceinline__ void prep_wdf_one(const float* __restrict__ w_down,
                                             __half* __restrict__ dst, int idx)
{
    int klo  = idx & 1;
    int q    = (idx >> 1) & 3;
    int lane = (idx >> 3) & 31;
    int mt   = (idx >> 8) & 3;
    int slab = idx >> 10;
    int g = lane >> 2, tq = lane & 3;
    int oc_l = 16 * mt + 8 * (q & 1) + g;
    {
        int grp = oc_l >> 4, r = oc_l & 15;
        oc_l = grp * 16 + ((r < 8) ? 2 * r : 2 * (r - 8) + 1);
    }
    int k = slab * 16 + 2 * (tq + 4 * (q >> 1)) + klo;
    int s = k >> 6;
    int c = k & 63;
    auto W = [&](int i, int ky, int kx) { return w_down[((oc_l * 128 + i) * 2 + ky) * 2 + kx]; };
    float v;
    if (s == 0)      v = W(2 * c, 0, 0) + W(2 * c + 1, 1, 1);
    else if (s == 1) v = W(2 * c, 0, 1) + W(2 * c + 1, 1, 0);
    else if (s == 2) v = W(2 * c, 1, 0) + W(2 * c + 1, 0, 1);
    else             v = W(2 * c, 1, 1) + W(2 * c + 1, 0, 0);
    dst[idx] = __float2half_rn(v);
}

// ---------------- single merged prep kernel ----------------
__global__ void prep_all_kernel(const float* __restrict__ w_hw, const float* __restrict__ w_cw,
                                const float* __restrict__ w_hc, const float* __restrict__ w_l1,
                                const float* __restrict__ w_l2, const float* __restrict__ w_hwc,
                                const float* __restrict__ w_down,
                                __half* wf_hw, __half* wf_cw, __half* wf_hc,
                                __half* wf_l1, __half* wf_l2, __half* w1h, __half* wdfh)
{
    int idx = blockIdx.x * 256 + threadIdx.x;
    if (idx < 36864) { prep_wf_one(w_hw, wf_hw, 64, idx, 0); return; }
    idx -= 36864;
    if (idx < 147456) { prep_wf_one(w_cw, wf_cw, 128, idx, 0); return; }
    idx -= 147456;
    if (idx < 147456) { prep_wf_one(w_hc, wf_hc, 128, idx, 0); return; }
    idx -= 147456;
    if (idx < 36864) { prep_wf_one(w_l1, wf_l1, 64, idx, 1); return; }
    idx -= 36864;
    if (idx < 36864) { prep_wf_one(w_l2, wf_l2, 64, idx, 0); return; }
    idx -= 36864;
    if (idx < 12288) { prep_w1_one(w_hwc, w1h, idx); return; }
    idx -= 12288;
    if (idx < 16384) { prep_wdf_one(w_down, wdfh, idx); return; }
}

// ---------------- merged x -> (xr pair-interleave, xt1 row-pair) ----------------
__global__ __launch_bounds__(256)
void pt1_kernel(const float* __restrict__ x, uint32_t* __restrict__ xr,
                uint32_t* __restrict__ xt1)
{
    int i = blockIdx.x * 256 + threadIdx.x;
    int w4 = i & 31;
    int hp = (i >> 5) & 63;
    int cp = (i >> 11) & 31;
    int b  = i >> 16;
    const float* pl0 = x + (b * 64 + 2 * cp) * HW_;
    const float* pl1 = pl0 + HW_;
    float4 a0 = *(const float4*)&pl0[(2 * hp) * 128 + 4 * w4];
    float4 a1 = *(const float4*)&pl0[(2 * hp + 1) * 128 + 4 * w4];
    float4 c0 = *(const float4*)&pl1[(2 * hp) * 128 + 4 * w4];
    float4 c1 = *(const float4*)&pl1[(2 * hp + 1) * 128 + 4 * w4];

    {
        __half2 h0 = __floats2half2_rn(a0.x, c0.x);
        __half2 h1 = __floats2half2_rn(a0.y, c0.y);
        __half2 h2 = __floats2half2_rn(a0.z, c0.z);
        __half2 h3 = __floats2half2_rn(a0.w, c0.w);
        *(uint4*)&xr[(b * 32 + cp) * HW_ + (2 * hp) * 128 + 4 * w4] =
            make_uint4(*(uint32_t*)&h0, *(uint32_t*)&h1, *(uint32_t*)&h2, *(uint32_t*)&h3);
        __half2 k0 = __floats2half2_rn(a1.x, c1.x);
        __half2 k1 = __floats2half2_rn(a1.y, c1.y);
        __half2 k2 = __floats2half2_rn(a1.z, c1.z);
        __half2 k3 = __floats2half2_rn(a1.w, c1.w);
        *(uint4*)&xr[(b * 32 + cp) * HW_ + (2 * hp + 1) * 128 + 4 * w4] =
            make_uint4(*(uint32_t*)&k0, *(uint32_t*)&k1, *(uint32_t*)&k2, *(uint32_t*)&k3);
    }
    {
        __half2 h0 = __floats2half2_rn(a0.x, a1.x);
        __half2 h1 = __floats2half2_rn(a0.y, a1.y);
        __half2 h2 = __floats2half2_rn(a0.z, a1.z);
        __half2 h3 = __floats2half2_rn(a0.w, a1.w);
        *(uint4*)&xt1[((b * 64 + hp) * 64 + 2 * cp) * 128 + 4 * w4] =
            make_uint4(*(uint32_t*)&h0, *(uint32_t*)&h1, *(uint32_t*)&h2, *(uint32_t*)&h3);
        __half2 k0 = __floats2half2_rn(c0.x, c1.x);
        __half2 k1 = __floats2half2_rn(c0.y, c1.y);
        __half2 k2 = __floats2half2_rn(c0.z, c1.z);
        __half2 k3 = __floats2half2_rn(c0.w, c1.w);
        *(uint4*)&xt1[((b * 64 + hp) * 64 + 2 * cp + 1) * 128 + 4 * w4] =
            make_uint4(*(uint32_t*)&k0, *(uint32_t*)&k1, *(uint32_t*)&k2, *(uint32_t*)&k3);
    }
}

// ---------------- t2: half2 [b][w/2][h][c] ----------------
__global__ __launch_bounds__(256)
void t2f_kernel(const float* __restrict__ x, uint32_t* __restrict__ o)
{
    __shared__ float tile[32][33];
    int tx = threadIdx.x, ty = threadIdx.y;
    int w0 = blockIdx.x * 32;
    int c0 = blockIdx.y * 32;
    int bh = blockIdx.z;
    int b = bh >> 7, hrow = bh & 127;
    int xb = b * CHW_ + hrow * 128;
#pragma unroll
    for (int i = 0; i < 4; i++)
        tile[ty + 8 * i][tx] = x[xb + (c0 + ty + 8 * i) * HW_ + w0 + tx];
    __syncthreads();
#pragma unroll
    for (int j = 0; j < 2; j++) {
        int wl = ty + 8 * j;
        __half2 hv = __floats2half2_rn(tile[tx][2 * wl], tile[tx][2 * wl + 1]);
        o[((b * 64 + (w0 >> 1) + wl) * 128 + hrow) * 64 + c0 + tx] = *(uint32_t*)&hv;
    }
}

// ---------------- conv1x1 via fp16 MMA ----------------
__global__ __launch_bounds__(256)
void gemm1x1_f16(const uint32_t* __restrict__ xh2, const __half* __restrict__ wprep,
                 const float* __restrict__ bias, __half* __restrict__ t)
{
    constexpr int SKB = 264;
    constexpr int ASLAB = 512;
    constexpr int BSLAB = 8 * SKB;
    __shared__ __align__(16) uint32_t sm[2 * (ASLAB + BSLAB)];
    uint32_t* wsm = sm;
    uint32_t* bsm = sm + 2 * ASLAB;

    const int tid = threadIdx.x;
    const int p0 = blockIdx.x * 256;
    const int oc0 = blockIdx.y * 64;
    const int b = blockIdx.z;
    const __half* wsrc = wprep + blockIdx.y * 4096;
    const uint32_t* xsrc = xh2 + b * (32 * HW_) + p0;

    auto stage = [&](int slab, int bufi) {
        uint32_t dA = (uint32_t)__cvta_generic_to_shared(wsm + bufi * ASLAB);
        uint32_t dB = (uint32_t)__cvta_generic_to_shared(bsm + bufi * BSLAB);
        const __half* sA = wsrc + slab * 1024;
        for (int i = tid; i < 128; i += 256)
            cp_async16(dA + (uint32_t)(i * 16), sA + i * 8, true);
        for (int i = tid; i < 512; i += 256) {
            int kp = i >> 6, j = i & 63;
            cp_async16(dB + (uint32_t)((kp * SKB + 4 * j) * 4),
                       xsrc + (slab * 8 + kp) * HW_ + 4 * j, true);
        }
        cp_commit();
    };

    stage(0, 0);

    const int lane = tid & 31, warp = tid >> 5;
    const int g = lane >> 2, tq = lane & 3;
    const int cb0 = warp * 32;
    const int afrag = lane * 4;

    float acc[4][4][4];
#pragma unroll
    for (int mt = 0; mt < 4; mt++)
#pragma unroll
        for (int nt = 0; nt < 4; nt++)
#pragma unroll
            for (int q = 0; q < 4; q++) acc[mt][nt][q] = 0.f;

    int buf = 0;
    for (int slab = 0; slab < 4; slab++) {
        cp_wait0();
        __syncthreads();
        if (slab + 1 < 4) stage(slab + 1, buf ^ 1);

        const uint32_t* wa = wsm + buf * ASLAB;
        const uint32_t* bb = bsm + buf * BSLAB;
        uint4 au4[4];
#pragma unroll
        for (int mt = 0; mt < 4; mt++)
            au4[mt] = *(const uint4*)&wa[mt * 128 + afrag];
        int bbase = tq * SKB + cb0 + g;
#pragma unroll
        for (int nt = 0; nt < 4; nt++) {
            uint32_t b0 = bb[bbase + 8 * nt];
            uint32_t b1 = bb[bbase + 4 * SKB + 8 * nt];
#pragma unroll
            for (int mt = 0; mt < 4; mt++)
                mma_f16(acc[mt][nt], (const uint32_t*)&au4[mt], b0, b1);
        }
        buf ^= 1;
    }

#pragma unroll
    for (int mt = 0; mt < 4; mt++) {
        const int oc = oc0 + 16 * mt + g;
        const float bv0 = bias[oc], bv1 = bias[oc + 8];
#pragma unroll
        for (int nt = 0; nt < 4; nt++) {
            const int pc = p0 + cb0 + 8 * nt + 2 * tq;
            int e0 = b * GBS_ + oc * HW_ + pc;
            int e1 = e0 + 8 * HW_;
            *(__half2*)&t[e0] = __floats2half2_rn(acc[mt][nt][0] + bv0, acc[mt][nt][1] + bv0);
            *(__half2*)&t[e1] = __floats2half2_rn(acc[mt][nt][2] + bv1, acc[mt][nt][3] + bv1);
        }
    }
}

// ---------------- depthwise 3x3: half in, half out ----------------
__global__ __launch_bounds__(256)
void dwconv_v3_kernel(const __half* __restrict__ t, const float* __restrict__ w_dw,
                      const float* __restrict__ b_dw, __half* __restrict__ g)
{
    __shared__ float xs[18][136];
    const int tid = threadIdx.x;
    const int s1_0 = blockIdx.x * 16;
    const int og = blockIdx.y, b = blockIdx.z;
    const int base = b * GBS_ + og * HW_;

    if (tid < 36) {
        int row = tid >> 1, side = tid & 1;
        xs[row][side ? 132 : 3] = 0.f;
    }
    for (int idx = tid; idx < 576; idx += 256) {
        int row = idx >> 5, q = idx & 31;
        int s1g = s1_0 - 1 + row;
        float4 v = make_float4(0.f, 0.f, 0.f, 0.f);
        if (s1g >= 0 && s1g < 128)
            v = h4_to_f4(*(const uint2*)&t[base + s1g * 128 + q * 4]);
        xs[row][4 + q * 4 + 0] = v.x;
        xs[row][4 + q * 4 + 1] = v.y;
        xs[row][4 + q * 4 + 2] = v.z;
        xs[row][4 + q * 4 + 3] = v.w;
    }
    __syncthreads();

    float w[9];
#pragma unroll
    for (int k = 0; k < 9; k++) w[k] = w_dw[og * 9 + k];
    float bb = b_dw[og];

    const int r = tid >> 4, cb = (tid & 15) * 8;
    float o[8];
#pragma unroll
    for (int j = 0; j < 8; j++) {
        float s = bb;
#pragma unroll
        for (int dr = 0; dr < 3; dr++)
#pragma unroll
            for (int dc = 0; dc < 3; dc++)
                s += w[dr * 3 + dc] * xs[r + dr][cb + j + 3 + dc];
        o[j] = s;
    }
    __half2 q0 = __floats2half2_rn(o[0], o[1]);
    __half2 q1 = __floats2half2_rn(o[2], o[3]);
    __half2 q2 = __floats2half2_rn(o[4], o[5]);
    __half2 q3 = __floats2half2_rn(o[6], o[7]);
    uint4 u = make_uint4(*(uint32_t*)&q0, *(uint32_t*)&q1, *(uint32_t*)&q2, *(uint32_t*)&q3);
    *(uint4*)&g[base + (s1_0 + r) * 128 + cb] = u;
}

// ---------------- fp16 tensor-core implicit-GEMM 3x3 conv ----------------
// OUTH: 0 fp32 planar (+RES), 1 half2 pair-interleaved (PERM), 2 half planar,
//       3 half staged-transpose for OUTV==1 (W=64 tiles)
template<int C, int S1, int W, int OUTV, int RES, int OUTH>
__global__ __launch_bounds__(256, 2)
void conv3x3_f16(const uint32_t* __restrict__ xh2, const __half* __restrict__ wprep,
                 const float* __restrict__ bias, void* __restrict__ outv,
                 const float* __restrict__ res,
                 int o_oc, int o_s1, int o_s2, int o_b)
{
    constexpr int TR = 256 / W;
    constexpr int NS = C / 16;
    constexpr int RW = W + 8;
    constexpr int SK = (TR + 2) * RW + 8;
    constexpr int ASLAB = 9 * 512;
    constexpr int BSLAB = 8 * SK;
    constexpr int BCH = W / 4;

    extern __shared__ uint32_t smu[];
    uint32_t* wsm = smu;
    uint32_t* bsm = smu + 2 * ASLAB;

    const int tid = threadIdx.x;
    const int s1_0 = blockIdx.x * TR;
    const int oc0 = blockIdx.y * 64;
    const int b = blockIdx.z;
    const uint32_t* xb = xh2 + b * ((C / 2) * S1 * W);
    const __half* wsrc = wprep + blockIdx.y * (NS * 9216);

    for (int i = tid; i < 2 * 8 * (TR + 2) * 2; i += 256) {
        int side = i & 1; int rest = i >> 1;
        int row = rest % (TR + 2); rest /= (TR + 2);
        int kp = rest & 7; int bufi = rest >> 3;
        bsm[bufi * BSLAB + kp * SK + row * RW + (side ? (W + 4) : 3)] = 0u;
    }

    auto stageA = [&](int slab, int bufi) {
        uint32_t d0 = (uint32_t)__cvta_generic_to_shared(wsm + bufi * ASLAB);
        const __half* src = wsrc + slab * 9216;
        for (int i = tid; i < 1152; i += 256)
            cp_async16(d0 + (uint32_t)(i * 16), src + i * 8, true);
    };
    auto stageB = [&](int slab, int bufi) {
        uint32_t d0 = (uint32_t)__cvta_generic_to_shared(bsm + bufi * BSLAB);
        const uint32_t* src = xb + slab * 8 * (S1 * W);
        for (int i = tid; i < 8 * (TR + 2) * BCH; i += 256) {
            int j = i % BCH; int rest = i / BCH;
            int row = rest % (TR + 2); int kp = rest / (TR + 2);
            int s1g = s1_0 - 1 + row;
            bool v = (s1g >= 0) && (s1g < S1);
            int s1c = v ? s1g : 0;
            cp_async16(d0 + (uint32_t)((kp * SK + row * RW + 4 + 4 * j) * 4),
                       src + kp * (S1 * W) + s1c * W + 4 * j, v);
        }
    };

    stageA(0, 0); stageB(0, 0); cp_commit();

    const int lane = tid & 31, warp = tid >> 5;
    const int g = lane >> 2, tq = lane & 3;
    const int rbase = (warp * 32) / W;
    const int cb0 = (warp * 32) % W;
    const int afrag = lane * 4;

    float acc[4][4][4];
#pragma unroll
    for (int mt = 0; mt < 4; mt++)
#pragma unroll
        for (int nt = 0; nt < 4; nt++)
#pragma unroll
            for (int q = 0; q < 4; q++) acc[mt][nt][q] = 0.f;

    int buf = 0;
    for (int slab = 0; slab < NS; slab++) {
        cp_wait0();
        __syncthreads();
        if (slab + 1 < NS) { stageA(slab + 1, buf ^ 1); stageB(slab + 1, buf ^ 1); cp_commit(); }

        const uint32_t* wa = wsm + buf * ASLAB;
        const uint32_t* bb = bsm + buf * BSLAB;
#pragma unroll
        for (int dr = 0; dr < 3; dr++) {
#pragma unroll
            for (int dc = 0; dc < 3; dc++) {
                const int s = dr * 3 + dc;
                uint4 au4[4];
                const uint32_t* wp = &wa[s * 512 + afrag];
#pragma unroll
                for (int mt = 0; mt < 4; mt++)
                    au4[mt] = *(const uint4*)&wp[mt * 128];
                int bbase = tq * SK + (rbase + dr) * RW + cb0 + g + dc + 3;
#pragma unroll
                for (int nt = 0; nt < 4; nt++) {
                    uint32_t b0 = bb[bbase + 8 * nt];
                    uint32_t b1 = bb[bbase + 4 * SK + 8 * nt];
#pragma unroll
                    for (int mt = 0; mt < 4; mt++)
                        mma_f16(acc[mt][nt], (const uint32_t*)&au4[mt], b0, b1);
                }
            }
        }
        buf ^= 1;
    }

    const int s1 = s1_0 + rbase;
    if (OUTH == 1) {
        uint32_t* outp = (uint32_t*)outv;
#pragma unroll
        for (int mt = 0; mt < 4; mt++) {
            const int ocb16 = oc0 + 16 * mt;
            const float bve = bias[ocb16 + 2 * g];
            const float bvo = bias[ocb16 + 2 * g + 1];
            const int ocp = (ocb16 >> 1) + g;
#pragma unroll
            for (int nt = 0; nt < 4; nt++) {
                const int px = cb0 + 8 * nt + 2 * tq;
                float v0 = lrelu(acc[mt][nt][0] + bve);
                float v1 = lrelu(acc[mt][nt][1] + bve);
                float v2 = lrelu(acc[mt][nt][2] + bvo);
                float v3 = lrelu(acc[mt][nt][3] + bvo);
                __half2 h0 = __floats2half2_rn(v0, v2);
                __half2 h1 = __floats2half2_rn(v1, v3);
                int e = b * o_b + ocp * o_oc + s1 * o_s1 + px;
                *(uint2*)&outp[e] = make_uint2(*(uint32_t*)&h0, *(uint32_t*)&h1);
            }
        }
    } else if (OUTH == 3) {
        // staged coalesced output for OUTV==1 (W==64): stage[s1l(4)][pc(64)][oc(72 pad)]
        __half* stg = (__half*)smu;
        __syncthreads();
#pragma unroll
        for (int mt = 0; mt < 4; mt++) {
            const int oc = 16 * mt + g;
            const float bv0 = bias[oc0 + oc], bv1 = bias[oc0 + oc + 8];
#pragma unroll
            for (int nt = 0; nt < 4; nt++) {
                const int pc = cb0 + 8 * nt + 2 * tq;
                __half* r0p = stg + (rbase * 64 + pc) * 72;
                __half* r1p = r0p + 72;
                r0p[oc]     = __float2half_rn(lrelu(acc[mt][nt][0] + bv0));
                r1p[oc]     = __float2half_rn(lrelu(acc[mt][nt][1] + bv0));
                r0p[oc + 8] = __float2half_rn(lrelu(acc[mt][nt][2] + bv1));
                r1p[oc + 8] = __float2half_rn(lrelu(acc[mt][nt][3] + bv1));
            }
        }
        __syncthreads();
        {
            int s1g = s1_0 + (tid >> 6);
            int pc = tid & 63;
            __half* outh = (__half*)outv;
            __half* dst = outh + b * o_b + pc * o_s2 + s1g * o_s1 + oc0;
            const uint4* srcp = (const uint4*)(stg + (size_t)tid * 72);
#pragma unroll
            for (int j = 0; j < 8; j++)
                *(uint4*)(dst + j * 8) = srcp[j];
        }
    } else if (OUTH == 2) {
        __half* outh = (__half*)outv;
#pragma unroll
        for (int mt = 0; mt < 4; mt++) {
            const int oc = oc0 + 16 * mt + g;
            const float bv0 = bias[oc], bv1 = bias[oc + 8];
#pragma unroll
            for (int nt = 0; nt < 4; nt++) {
                const int pc = cb0 + 8 * nt + 2 * tq;
                float v0 = lrelu(acc[mt][nt][0] + bv0);
                float v1 = lrelu(acc[mt][nt][1] + bv0);
                float v2 = lrelu(acc[mt][nt][2] + bv1);
                float v3 = lrelu(acc[mt][nt][3] + bv1);
                int e0 = b * o_b + oc * o_oc + s1 * o_s1 + pc;
                int e1 = e0 + 8 * o_oc;
                *(__half2*)&outh[e0] = __floats2half2_rn(v0, v1);
                *(__half2*)&outh[e1] = __floats2half2_rn(v2, v3);
            }
        }
    } else {
        float* out = (float*)outv;
#pragma unroll
        for (int mt = 0; mt < 4; mt++) {
            const int oc = oc0 + 16 * mt + g;
            const float bv0 = bias[oc], bv1 = bias[oc + 8];
#pragma unroll
            for (int nt = 0; nt < 4; nt++) {
                const int pc = cb0 + 8 * nt + 2 * tq;
                float v0 = lrelu(acc[mt][nt][0] + bv0);
                float v1 = lrelu(acc[mt][nt][1] + bv0);
                float v2 = lrelu(acc[mt][nt][2] + bv1);
                float v3 = lrelu(acc[mt][nt][3] + bv1);
                int e0 = b * o_b + oc * o_oc + s1 * o_s1 + pc;
                int e1 = e0 + 8 * o_oc;
                if (RES) {
                    v0 += res[e0]; v1 += res[e0 + 1];
                    v2 += res[e1]; v3 += res[e1 + 1];
                }
                *(float2*)&out[e0] = make_float2(v0, v1);
                *(float2*)&out[e1] = make_float2(v2, v3);
            }
        }
    }
}

// ---------------- down-GEMM ----------------
__global__ __launch_bounds__(256)
void gemm_down_f16(const uint32_t* __restrict__ xr, const __half* __restrict__ g,
                   const __half* __restrict__ xhw, const __half* __restrict__ xcw,
                   const __half* __restrict__ xhc, const __half* __restrict__ wdf,
                   const float* __restrict__ b_down, uint32_t* __restrict__ midh2)
{
    constexpr int SKB = 264;
    __shared__ __align__(16) uint32_t asmem[16 * 512];
    __shared__ __align__(16) uint32_t bsm[2 * 8 * SKB];

    const int tid = threadIdx.x;
    const int p0 = blockIdx.x * 256;
    const int b = blockIdx.z;

    {
        uint32_t dA = (uint32_t)__cvta_generic_to_shared(asmem);
        for (int i = tid; i < 2048; i += 256)
            cp_async16(dA + (uint32_t)(i * 16), wdf + i * 8, true);
        cp_commit();
    }

    const int lane = tid & 31, warp = tid >> 5;
    const int gq = lane >> 2, tq = lane & 3;
    const int cb0 = warp * 32;

    const int kp = tid >> 5;
    const int pxc = (tid & 31) * 8;
    const int pxg = p0 + pxc;

    uint4 r0, r1, r2, r3;

    auto loadRegs = [&](int s) {
        if (s < 4) {
            const uint32_t* src = xr + (b * 32 + s * 8 + kp) * HW_ + pxg;
            r0 = *(const uint4*)src;
            r1 = *(const uint4*)(src + 4);
        } else {
            int s4 = s - 4;
            int gc = 16 * s4 + 2 * kp;
            const __half* gp0 = g + (b * 192 + gc) * HW_ + pxg;
            const __half* br = (s4 < 4) ? xhw : ((s4 < 8) ? xcw : xhc);
            int bc = (s4 & 3) * 16 + 2 * kp;
            const __half* bp0 = br + (b * 64 + bc) * HW_ + pxg;
            r0 = *(const uint4*)gp0;
            r1 = *(const uint4*)(gp0 + HW_);
            r2 = *(const uint4*)bp0;
            r3 = *(const uint4*)(bp0 + HW_);
        }
    };
    auto stsRegs = [&](int s, int bufi) {
        uint32_t* dst = bsm + bufi * (8 * SKB) + kp * SKB + pxc;
        if (s < 4) {
            *(uint4*)dst = r0;
            *(uint4*)(dst + 4) = r1;
        } else {
            const __half* G0 = (const __half*)&r0;
            const __half* G1 = (const __half*)&r1;
            const __half* B0 = (const __half*)&r2;
            const __half* B1 = (const __half*)&r3;
            uint32_t o[8];
#pragma unroll
            for (int j = 0; j < 8; j++) {
                __half2 h = __floats2half2_rn(
                    __half2float(G0[j]) * __half2float(B0[j]),
                    __half2float(G1[j]) * __half2float(B1[j]));
                o[j] = *(uint32_t*)&h;
            }
            *(uint4*)dst = make_uint4(o[0], o[1], o[2], o[3]);
            *(uint4*)(dst + 4) = make_uint4(o[4], o[5], o[6], o[7]);
        }
    };

    float acc[4][4][4];
#pragma unroll
    for (int mt = 0; mt < 4; mt++)
#pragma unroll
        for (int nt = 0; nt < 4; nt++)
#pragma unroll
            for (int q = 0; q < 4; q++) acc[mt][nt][q] = 0.f;

    cp_wait0();
    loadRegs(0);
    stsRegs(0, 0);
    __syncthreads();

    int buf = 0;
    for (int s = 0; s < 16; s++) {
        if (s + 1 < 16) loadRegs(s + 1);
        const uint32_t* wa = asmem + s * 512;
        uint4 au4[4];
#pragma unroll
        for (int mt = 0; mt < 4; mt++)
            au4[mt] = *(const uint4*)&wa[mt * 128 + lane * 4];
        const uint32_t* bb = bsm + buf * (8 * SKB);
        int bbase = tq * SKB + cb0 + gq;
#pragma unroll
        for (int nt = 0; nt < 4; nt++) {
            uint32_t b0 = bb[bbase + 8 * nt];
            uint32_t b1 = bb[bbase + 4 * SKB + 8 * nt];
#pragma unroll
            for (int mt = 0; mt < 4; mt++)
                mma_f16(acc[mt][nt], (const uint32_t*)&au4[mt], b0, b1);
        }
        if (s + 1 < 16) {
            stsRegs(s + 1, buf ^ 1);
            __syncthreads();
        }
        buf ^= 1;
    }

#pragma unroll
    for (int mt = 0; mt < 4; mt++) {
        const float be = b_down[16 * mt + 2 * gq];
        const float bo = b_down[16 * mt + 2 * gq + 1];
        const int ocp = 8 * mt + gq;
#pragma unroll
        for (int nt = 0; nt < 4; nt++) {
            const int pc = p0 + cb0 + 8 * nt + 2 * tq;
            uint2 xres = *(const uint2*)&xr[(b * 32 + ocp) * HW_ + pc];
            float2 xa = __half22float2(*(__half2*)&xres.x);
            float2 xb2 = __half22float2(*(__half2*)&xres.y);
            float v0 = acc[mt][nt][0] + be + xa.x;
            float v2 = acc[mt][nt][2] + bo + xa.y;
            float v1 = acc[mt][nt][1] + be + xb2.x;
            float v3 = acc[mt][nt][3] + bo + xb2.y;
            __half2 m0 = __floats2half2_rn(v0, v2);
            __half2 m1 = __floats2half2_rn(v1, v3);
            *(uint2*)&midh2[(b * 32 + ocp) * HW_ + pc] =
                make_uint2(*(uint32_t*)&m0, *(uint32_t*)&m1);
        }
    }
}

// ---------------- stream/event pool ----------------
struct AsyncCtx {
    cudaStream_t s1, s2, s3;
    cudaEvent_t eRoot, eR4, ePrep, eCw, eHc, eHw;
    bool ok;
    AsyncCtx() {
        ok = true;
        ok &= (cudaStreamCreateWithFlags(&s1, cudaStreamNonBlocking) == cudaSuccess);
        ok &= (cudaStreamCreateWithFlags(&s2, cudaStreamNonBlocking) == cudaSuccess);
        ok &= (cudaStreamCreateWithFlags(&s3, cudaStreamNonBlocking) == cudaSuccess);
        ok &= (cudaEventCreateWithFlags(&eRoot, cudaEventDisableTiming) == cudaSuccess);
        ok &= (cudaEventCreateWithFlags(&eR4, cudaEventDisableTiming) == cudaSuccess);
        ok &= (cudaEventCreateWithFlags(&ePrep, cudaEventDisableTiming) == cudaSuccess);
        ok &= (cudaEventCreateWithFlags(&eCw, cudaEventDisableTiming) == cudaSuccess);
        ok &= (cudaEventCreateWithFlags(&eHc, cudaEventDisableTiming) == cudaSuccess);
        ok &= (cudaEventCreateWithFlags(&eHw, cudaEventDisableTiming) == cudaSuccess);
    }
};

// ---------------- launch ----------------
extern "C" void kernel_launch(void* const* d_in, const int* in_sizes, int n_in,
                              void* d_out, int out_size)
{
    const float* x      = (const float*)d_in[0];
    const float* w_hwc  = (const float*)d_in[1];
    const float* b_hwc  = (const float*)d_in[2];
    const float* w_dw   = (const float*)d_in[3];
    const float* b_dw   = (const float*)d_in[4];
    const float* w_hw   = (const float*)d_in[5];
    const float* b_hw   = (const float*)d_in[6];
    const float* w_cw   = (const float*)d_in[7];
    const float* b_cw   = (const float*)d_in[8];
    const float* w_hc   = (const float*)d_in[9];
    const float* b_hc   = (const float*)d_in[10];
    const float* w_down = (const float*)d_in[11];
    const float* b_down = (const float*)d_in[12];
    const float* w_l1   = (const float*)d_in[13];
    const float* b_l1   = (const float*)d_in[14];
    const float* w_l2   = (const float*)d_in[15];
    const float* b_l2   = (const float*)d_in[16];
    float* out = (float*)d_out;

    __half *t, *g, *xhw, *xcw, *xhc;
    uint32_t *xt1, *xt2, *xr, *mid, *o1;
    __half *wrh, *w1h, *wdfh;
    { void* p;
      cudaGetSymbolAddress(&p, d_t);   t   = (__half*)p;
      cudaGetSymbolAddress(&p, d_g);   g   = (__half*)p;
      cudaGetSymbolAddress(&p, d_xt1); xt1 = (uint32_t*)p;
      cudaGetSymbolAddress(&p, d_xt2); xt2 = (uint32_t*)p;
      cudaGetSymbolAddress(&p, d_xr);  xr  = (uint32_t*)p;
      cudaGetSymbolAddress(&p, d_xhw); xhw = (__half*)p;
      cudaGetSymbolAddress(&p, d_xcw); xcw = (__half*)p;
      cudaGetSymbolAddress(&p, d_xhc); xhc = (__half*)p;
      cudaGetSymbolAddress(&p, d_mid); mid = (uint32_t*)p;
      cudaGetSymbolAddress(&p, d_o1);  o1  = (uint32_t*)p;
      cudaGetSymbolAddress(&p, d_wr);  wrh = (__half*)p;
      cudaGetSymbolAddress(&p, d_w1);  w1h = (__half*)p;
      cudaGetSymbolAddress(&p, d_wdf); wdfh = (__half*)p;
    }

    __half* wf_hw = wrh;
    __half* wf_cw = wrh + 36864;
    __half* wf_hc = wrh + 184320;
    __half* wf_l1 = wrh + 331776;
    __half* wf_l2 = wrh + 368640;

    const int SM128 = (2 * 4608 + 2 * (8 * ((2 + 2) * 136 + 8))) * 4;  // 72192
    const int SM64  = (2 * 4608 + 2 * (8 * ((4 + 2) * 72 + 8))) * 4;   // 65024

    cudaFuncSetAttribute((const void*)conv3x3_f16<64, 128, 128, 0, 0, 2>,
                         cudaFuncAttributeMaxDynamicSharedMemorySize, SM128);
    cudaFuncSetAttribute((const void*)conv3x3_f16<128, 64, 128, 0, 0, 2>,
                         cudaFuncAttributeMaxDynamicSharedMemorySize, SM128);
    cudaFuncSetAttribute((const void*)conv3x3_f16<128, 128, 64, 1, 0, 3>,
                         cudaFuncAttributeMaxDynamicSharedMemorySize, SM64);
    cudaFuncSetAttribute((const void*)conv3x3_f16<64, 128, 128, 0, 0, 1>,
                         cudaFuncAttributeMaxDynamicSharedMemorySize, SM128);
    cudaFuncSetAttribute((const void*)conv3x3_f16<64, 128, 128, 0, 1, 0>,
                         cudaFuncAttributeMaxDynamicSharedMemorySize, SM128);

    static AsyncCtx ctx;

    if (ctx.ok) {
        cudaStream_t m = 0;
        cudaEventRecord(ctx.eRoot, m);
        cudaStreamWaitEvent(ctx.s1, ctx.eRoot, 0);
        cudaStreamWaitEvent(ctx.s2, ctx.eRoot, 0);
        cudaStreamWaitEvent(ctx.s3, ctx.eRoot, 0);

        // s3: one merged weight prep
        prep_all_kernel<<<1696, 256, 0, ctx.s3>>>(w_hw, w_cw, w_hc, w_l1, w_l2, w_hwc, w_down,
                                                  wf_hw, wf_cw, wf_hc, wf_l1, wf_l2, w1h, wdfh);
        cudaEventRecord(ctx.ePrep, ctx.s3);

        // main: merged xr+xt1 prep
        pt1_kernel<<<2048, 256, 0, m>>>(x, xr, xt1);
        cudaEventRecord(ctx.eR4, m);

        // s2: t2f early, then hc conv
        t2f_kernel<<<dim3(4, 2, 1024), dim3(32, 8), 0, ctx.s2>>>(x, xt2);
        cudaStreamWaitEvent(ctx.s2, ctx.ePrep, 0);
        conv3x3_f16<128, 128, 64, 1, 0, 3><<<dim3(32, 2, 8), 256, SM64, ctx.s2>>>(
            xt2, wf_hc, b_hc, xhc, nullptr, 1, 128, HW_, CHW_);
        cudaEventRecord(ctx.eHc, ctx.s2);

        // s1: cw conv (needs xt1 + prep)
        cudaStreamWaitEvent(ctx.s1, ctx.ePrep, 0);
        cudaStreamWaitEvent(ctx.s1, ctx.eR4, 0);
        conv3x3_f16<128, 64, 128, 0, 0, 2><<<dim3(32, 2, 8), 256, SM128, ctx.s1>>>(
            xt1, wf_cw, b_cw, xcw, nullptr, 128, HW_, 1, CHW_);
        cudaEventRecord(ctx.eCw, ctx.s1);

        // s3: hw conv (needs xr + prep; prep on same stream)
        cudaStreamWaitEvent(ctx.s3, ctx.eR4, 0);
        conv3x3_f16<64, 128, 128, 0, 0, 2><<<dim3(64, 1, 8), 256, SM128, ctx.s3>>>(
            xr, wf_hw, b_hw, xhw, nullptr, HW_, 128, 1, CHW_);
        cudaEventRecord(ctx.eHw, ctx.s3);

        // main: gate path (needs prep for w1h)
        cudaStreamWaitEvent(m, ctx.ePrep, 0);
        gemm1x1_f16<<<dim3(64, 3, 8), 256, 0, m>>>(xr, w1h, b_hwc, t);
        dwconv_v3_kernel<<<dim3(8, 192, 8), 256, 0, m>>>(t, w_dw, b_dw, g);

        // join
        cudaStreamWaitEvent(m, ctx.eCw, 0);
        cudaStreamWaitEvent(m, ctx.eHc, 0);
        cudaStreamWaitEvent(m, ctx.eHw, 0);

        gemm_down_f16<<<dim3(64, 1, 8), 256, 0, m>>>(xr, g, xhw, xcw, xhc, wdfh, b_down, mid);
        conv3x3_f16<64, 128, 128, 0, 0, 1><<<dim3(64, 1, 8), 256, SM128, m>>>(
            mid, wf_l1, b_l1, o1, nullptr, HW_, 128, 1, 32 * HW_);
        conv3x3_f16<64, 128, 128, 0, 1, 0><<<dim3(64, 1, 8), 256, SM128, m>>>(
            o1, wf_l2, b_l2, out, x, HW_, 128, 1, CHW_);
    } else {
        // serial fallback
        prep_all_kernel<<<1696, 256>>>(w_hw, w_cw, w_hc, w_l1, w_l2, w_hwc, w_down,
                                       wf_hw, wf_cw, wf_hc, wf_l1, wf_l2, w1h, wdfh);
        pt1_kernel<<<2048, 256>>>(x, xr, xt1);
        t2f_kernel<<<dim3(4, 2, 1024), dim3(32, 8)>>>(x, xt2);
        gemm1x1_f16<<<dim3(64, 3, 8), 256>>>(xr, w1h, b_hwc, t);
        dwconv_v3_kernel<<<dim3(8, 192, 8), 256>>>(t, w_dw, b_dw, g);
        conv3x3_f16<64, 128, 128, 0, 0, 2><<<dim3(64, 1, 8), 256, SM128>>>(
            xr, wf_hw, b_hw, xhw, nullptr, HW_, 128, 1, CHW_);
        conv3x3_f16<128, 64, 128, 0, 0, 2><<<dim3(32, 2, 8), 256, SM128>>>(
            xt1, wf_cw, b_cw, xcw, nullptr, 128, HW_, 1, CHW_);
        conv3x3_f16<128, 128, 64, 1, 0, 3><<<dim3(32, 2, 8), 256, SM64>>>(
            xt2, wf_hc, b_hc, xhc, nullptr, 1, 128, HW_, CHW_);
        gemm_down_f16<<<dim3(64, 1, 8), 256>>>(xr, g, xhw, xcw, xhc, wdfh, b_down, mid);
        conv3x3_f16<64, 128, 128, 0, 0, 1><<<dim3(64, 1, 8), 256, SM128>>>(
            mid, wf_l1, b_l1, o1, nullptr, HW_, 128, 1, 32 * HW_);
        conv3x3_f16<64, 128, 128, 0, 1, 0><<<dim3(64, 1, 8), 256, SM128>>>(
            o1, wf_l2, b_l2, out, x, HW_, 128, 1, CHW_);
    }
}

// round 16
// speedup vs baseline: 1.0521x; 1.0521x over previous
#include <cuda_runtime.h>
#include <cuda_fp16.h>
#include <cstdint>

// B=8, C=64, T=128
#define HW_   16384
#define CHW_  1048576
#define GBS_  3145728

typedef unsigned long long ull;

// ---------------- scratch ----------------
__device__ float d_t  [12582912];  // half [8,192,128,128] conv1x1 out
__device__ float d_g  [12582912];  // half [8,192,128,128] gates (planar)
__device__ float d_xt1[8388608];   // half2 [b][h/2][c][w]
__device__ float d_xt2[8388608];   // half2 [b][w/2][h][c]
__device__ float d_xr [8388608];   // half2 [b][c/2][h][w]
__device__ float d_xhw[4194304];   // half planar [b][c][h][w]
__device__ float d_xcw[4194304];
__device__ float d_xhc[4194304];
__device__ float d_mid[8388608];   // half2 [b][c/2][h][w]
__device__ float d_o1 [8388608];   // half2 [b][c/2][h][w]
__device__ float d_wr [405504];    // fp16 conv weights (lane-fragment order)
__device__ float d_w1 [12288];     // fp16 1x1 weights
__device__ float d_wdf[8192];      // fp16 down-GEMM weights

__device__ __forceinline__ float lrelu(float v) { return v > 0.f ? v : 0.1f * v; }

__device__ __forceinline__ void cp_async16(uint32_t dst, const void* src, bool valid) {
    int sz = valid ? 16 : 0;
    asm volatile("cp.async.cg.shared.global [%0], [%1], 16, %2;\n"
                 :: "r"(dst), "l"(src), "r"(sz));
}
__device__ __forceinline__ void cp_commit() { asm volatile("cp.async.commit_group;\n"); }
__device__ __forceinline__ void cp_wait0()  { asm volatile("cp.async.wait_group 0;\n"); }

__device__ __forceinline__ float4 h4_to_f4(uint2 u) {
    float2 a = __half22float2(*(__half2*)&u.x);
    float2 b = __half22float2(*(__half2*)&u.y);
    return make_float4(a.x, a.y, b.x, b.y);
}

// ---------------- fp16 mma (m16n8k16, fp32 accum) ----------------
__device__ __forceinline__ void mma_f16(float* d, const uint32_t* a,
                                        uint32_t b0, uint32_t b1) {
    asm volatile("mma.sync.aligned.m16n8k16.row.col.f32.f16.f16.f32 "
                 "{%0,%1,%2,%3}, {%4,%5,%6,%7}, {%8,%9}, {%0,%1,%2,%3};"
                 : "+f"(d[0]), "+f"(d[1]), "+f"(d[2]), "+f"(d[3])
                 : "r"(a[0]), "r"(a[1]), "r"(a[2]), "r"(a[3]), "r"(b0), "r"(b1));
}

// ---------------- prep kernels (lane-fragment order) ----------------
__global__ void prep_wf_kernel(const float* __restrict__ src, __half* __restrict__ dst,
                               int OC, int C, int PERM)
{
    int idx = blockIdx.x * 256 + threadIdx.x;
    int total = OC * C * 9;
    if (idx >= total) return;
    int klo  = idx & 1;
    int q    = (idx >> 1) & 3;
    int lane = (idx >> 3) & 31;
    int mt   = (idx >> 8) & 3;
    int s    = (idx >> 10) % 9;
    int rest = idx / 9216;
    int NS = C >> 4;
    int slab = rest % NS;
    int ocb = rest / NS;
    int g = lane >> 2, tq = lane & 3;
    int oc_l = 16 * mt + 8 * (q & 1) + g;
    if (PERM) {
        int grp = oc_l >> 4, r = oc_l & 15;
        oc_l = grp * 16 + ((r < 8) ? 2 * r : 2 * (r - 8) + 1);
    }
    int k = slab * 16 + 2 * (tq + 4 * (q >> 1)) + klo;
    dst[idx] = __float2half_rn(src[((ocb * 64 + oc_l) * C + k) * 9 + s]);
}

__global__ void prep_w1f_kernel(const float* __restrict__ src, __half* __restrict__ dst)
{
    int idx = blockIdx.x * 256 + threadIdx.x;
    if (idx >= 12288) return;
    int klo  = idx & 1;
    int q    = (idx >> 1) & 3;
    int lane = (idx >> 3) & 31;
    int mt   = (idx >> 8) & 3;
    int slab = (idx >> 10) & 3;
    int ocb  = idx >> 12;
    int g = lane >> 2, tq = lane & 3;
    int oc_l = 16 * mt + 8 * (q & 1) + g;
    int k = slab * 16 + 2 * (tq + 4 * (q >> 1)) + klo;
    dst[idx] = __float2half_rn(src[(ocb * 64 + oc_l) * 64 + k]);
}

__global__ void prep_wdf_kernel(const float* __restrict__ w_down, __half* __restrict__ dst)
{
    int idx = blockIdx.x * 256 + threadIdx.x;
    if (idx >= 16384) return;
    int klo  = idx & 1;
    int q    = (idx >> 1) & 3;
    int lane = (idx >> 3) & 31;
    int mt   = (idx >> 8) & 3;
    int slab = idx >> 10;
    int g = lane >> 2, tq = lane & 3;
    int oc_l = 16 * mt + 8 * (q & 1) + g;
    {
        int grp = oc_l >> 4, r = oc_l & 15;
        oc_l = grp * 16 + ((r < 8) ? 2 * r : 2 * (r - 8) + 1);
    }
    int k = slab * 16 + 2 * (tq + 4 * (q >> 1)) + klo;
    int s = k >> 6;
    int c = k & 63;
    auto W = [&](int i, int ky, int kx) { return w_down[((oc_l * 128 + i) * 2 + ky) * 2 + kx]; };
    float v;
    if (s == 0)      v = W(2 * c, 0, 0) + W(2 * c + 1, 1, 1);
    else if (s == 1) v = W(2 * c, 0, 1) + W(2 * c + 1, 1, 0);
    else if (s == 2) v = W(2 * c, 1, 0) + W(2 * c + 1, 0, 1);
    else             v = W(2 * c, 1, 1) + W(2 * c + 1, 0, 0);
    dst[idx] = __float2half_rn(v);
}

// ---------------- merged x -> (xr pair-interleave, xt1 row-pair) ----------------
__global__ __launch_bounds__(256)
void pt1_kernel(const float* __restrict__ x, uint32_t* __restrict__ xr,
                uint32_t* __restrict__ xt1)
{
    int i = blockIdx.x * 256 + threadIdx.x;
    int w4 = i & 31;
    int hp = (i >> 5) & 63;
    int cp = (i >> 11) & 31;
    int b  = i >> 16;
    const float* pl0 = x + (b * 64 + 2 * cp) * HW_;
    const float* pl1 = pl0 + HW_;
    float4 a0 = *(const float4*)&pl0[(2 * hp) * 128 + 4 * w4];
    float4 a1 = *(const float4*)&pl0[(2 * hp + 1) * 128 + 4 * w4];
    float4 c0 = *(const float4*)&pl1[(2 * hp) * 128 + 4 * w4];
    float4 c1 = *(const float4*)&pl1[(2 * hp + 1) * 128 + 4 * w4];

    {
        __half2 h0 = __floats2half2_rn(a0.x, c0.x);
        __half2 h1 = __floats2half2_rn(a0.y, c0.y);
        __half2 h2 = __floats2half2_rn(a0.z, c0.z);
        __half2 h3 = __floats2half2_rn(a0.w, c0.w);
        *(uint4*)&xr[(b * 32 + cp) * HW_ + (2 * hp) * 128 + 4 * w4] =
            make_uint4(*(uint32_t*)&h0, *(uint32_t*)&h1, *(uint32_t*)&h2, *(uint32_t*)&h3);
        __half2 k0 = __floats2half2_rn(a1.x, c1.x);
        __half2 k1 = __floats2half2_rn(a1.y, c1.y);
        __half2 k2 = __floats2half2_rn(a1.z, c1.z);
        __half2 k3 = __floats2half2_rn(a1.w, c1.w);
        *(uint4*)&xr[(b * 32 + cp) * HW_ + (2 * hp + 1) * 128 + 4 * w4] =
            make_uint4(*(uint32_t*)&k0, *(uint32_t*)&k1, *(uint32_t*)&k2, *(uint32_t*)&k3);
    }
    {
        __half2 h0 = __floats2half2_rn(a0.x, a1.x);
        __half2 h1 = __floats2half2_rn(a0.y, a1.y);
        __half2 h2 = __floats2half2_rn(a0.z, a1.z);
        __half2 h3 = __floats2half2_rn(a0.w, a1.w);
        *(uint4*)&xt1[((b * 64 + hp) * 64 + 2 * cp) * 128 + 4 * w4] =
            make_uint4(*(uint32_t*)&h0, *(uint32_t*)&h1, *(uint32_t*)&h2, *(uint32_t*)&h3);
        __half2 k0 = __floats2half2_rn(c0.x, c1.x);
        __half2 k1 = __floats2half2_rn(c0.y, c1.y);
        __half2 k2 = __floats2half2_rn(c0.z, c1.z);
        __half2 k3 = __floats2half2_rn(c0.w, c1.w);
        *(uint4*)&xt1[((b * 64 + hp) * 64 + 2 * cp + 1) * 128 + 4 * w4] =
            make_uint4(*(uint32_t*)&k0, *(uint32_t*)&k1, *(uint32_t*)&k2, *(uint32_t*)&k3);
    }
}

// ---------------- t2: half2 [b][w/2][h][c] ----------------
__global__ __launch_bounds__(256)
void t2f_kernel(const float* __restrict__ x, uint32_t* __restrict__ o)
{
    __shared__ float tile[32][33];
    int tx = threadIdx.x, ty = threadIdx.y;
    int w0 = blockIdx.x * 32;
    int c0 = blockIdx.y * 32;
    int bh = blockIdx.z;
    int b = bh >> 7, hrow = bh & 127;
    int xb = b * CHW_ + hrow * 128;
#pragma unroll
    for (int i = 0; i < 4; i++)
        tile[ty + 8 * i][tx] = x[xb + (c0 + ty + 8 * i) * HW_ + w0 + tx];
    __syncthreads();
#pragma unroll
    for (int j = 0; j < 2; j++) {
        int wl = ty + 8 * j;
        __half2 hv = __floats2half2_rn(tile[tx][2 * wl], tile[tx][2 * wl + 1]);
        o[((b * 64 + (w0 >> 1) + wl) * 128 + hrow) * 64 + c0 + tx] = *(uint32_t*)&hv;
    }
}

// ---------------- conv1x1 via fp16 MMA ----------------
__global__ __launch_bounds__(256)
void gemm1x1_f16(const uint32_t* __restrict__ xh2, const __half* __restrict__ wprep,
                 const float* __restrict__ bias, __half* __restrict__ t)
{
    constexpr int SKB = 264;
    constexpr int ASLAB = 512;
    constexpr int BSLAB = 8 * SKB;
    __shared__ __align__(16) uint32_t sm[2 * (ASLAB + BSLAB)];
    uint32_t* wsm = sm;
    uint32_t* bsm = sm + 2 * ASLAB;

    const int tid = threadIdx.x;
    const int p0 = blockIdx.x * 256;
    const int oc0 = blockIdx.y * 64;
    const int b = blockIdx.z;
    const __half* wsrc = wprep + blockIdx.y * 4096;
    const uint32_t* xsrc = xh2 + b * (32 * HW_) + p0;

    auto stage = [&](int slab, int bufi) {
        uint32_t dA = (uint32_t)__cvta_generic_to_shared(wsm + bufi * ASLAB);
        uint32_t dB = (uint32_t)__cvta_generic_to_shared(bsm + bufi * BSLAB);
        const __half* sA = wsrc + slab * 1024;
        for (int i = tid; i < 128; i += 256)
            cp_async16(dA + (uint32_t)(i * 16), sA + i * 8, true);
        for (int i = tid; i < 512; i += 256) {
            int kp = i >> 6, j = i & 63;
            cp_async16(dB + (uint32_t)((kp * SKB + 4 * j) * 4),
                       xsrc + (slab * 8 + kp) * HW_ + 4 * j, true);
        }
        cp_commit();
    };

    stage(0, 0);

    const int lane = tid & 31, warp = tid >> 5;
    const int g = lane >> 2, tq = lane & 3;
    const int cb0 = warp * 32;
    const int afrag = lane * 4;

    float acc[4][4][4];
#pragma unroll
    for (int mt = 0; mt < 4; mt++)
#pragma unroll
        for (int nt = 0; nt < 4; nt++)
#pragma unroll
            for (int q = 0; q < 4; q++) acc[mt][nt][q] = 0.f;

    int buf = 0;
    for (int slab = 0; slab < 4; slab++) {
        cp_wait0();
        __syncthreads();
        if (slab + 1 < 4) stage(slab + 1, buf ^ 1);

        const uint32_t* wa = wsm + buf * ASLAB;
        const uint32_t* bb = bsm + buf * BSLAB;
        uint4 au4[4];
#pragma unroll
        for (int mt = 0; mt < 4; mt++)
            au4[mt] = *(const uint4*)&wa[mt * 128 + afrag];
        int bbase = tq * SKB + cb0 + g;
#pragma unroll
        for (int nt = 0; nt < 4; nt++) {
            uint32_t b0 = bb[bbase + 8 * nt];
            uint32_t b1 = bb[bbase + 4 * SKB + 8 * nt];
#pragma unroll
            for (int mt = 0; mt < 4; mt++)
                mma_f16(acc[mt][nt], (const uint32_t*)&au4[mt], b0, b1);
        }
        buf ^= 1;
    }

#pragma unroll
    for (int mt = 0; mt < 4; mt++) {
        const int oc = oc0 + 16 * mt + g;
        const float bv0 = bias[oc], bv1 = bias[oc + 8];
#pragma unroll
        for (int nt = 0; nt < 4; nt++) {
            const int pc = p0 + cb0 + 8 * nt + 2 * tq;
            int e0 = b * GBS_ + oc * HW_ + pc;
            int e1 = e0 + 8 * HW_;
            *(__half2*)&t[e0] = __floats2half2_rn(acc[mt][nt][0] + bv0, acc[mt][nt][1] + bv0);
            *(__half2*)&t[e1] = __floats2half2_rn(acc[mt][nt][2] + bv1, acc[mt][nt][3] + bv1);
        }
    }
}

// ---------------- depthwise 3x3: half in, half out ----------------
__global__ __launch_bounds__(256)
void dwconv_v3_kernel(const __half* __restrict__ t, const float* __restrict__ w_dw,
                      const float* __restrict__ b_dw, __half* __restrict__ g)
{
    __shared__ float xs[18][136];
    const int tid = threadIdx.x;
    const int s1_0 = blockIdx.x * 16;
    const int og = blockIdx.y, b = blockIdx.z;
    const int base = b * GBS_ + og * HW_;

    if (tid < 36) {
        int row = tid >> 1, side = tid & 1;
        xs[row][side ? 132 : 3] = 0.f;
    }
    for (int idx = tid; idx < 576; idx += 256) {
        int row = idx >> 5, q = idx & 31;
        int s1g = s1_0 - 1 + row;
        float4 v = make_float4(0.f, 0.f, 0.f, 0.f);
        if (s1g >= 0 && s1g < 128)
            v = h4_to_f4(*(const uint2*)&t[base + s1g * 128 + q * 4]);
        xs[row][4 + q * 4 + 0] = v.x;
        xs[row][4 + q * 4 + 1] = v.y;
        xs[row][4 + q * 4 + 2] = v.z;
        xs[row][4 + q * 4 + 3] = v.w;
    }
    __syncthreads();

    float w[9];
#pragma unroll
    for (int k = 0; k < 9; k++) w[k] = w_dw[og * 9 + k];
    float bb = b_dw[og];

    const int r = tid >> 4, cb = (tid & 15) * 8;
    float o[8];
#pragma unroll
    for (int j = 0; j < 8; j++) {
        float s = bb;
#pragma unroll
        for (int dr = 0; dr < 3; dr++)
#pragma unroll
            for (int dc = 0; dc < 3; dc++)
                s += w[dr * 3 + dc] * xs[r + dr][cb + j + 3 + dc];
        o[j] = s;
    }
    __half2 q0 = __floats2half2_rn(o[0], o[1]);
    __half2 q1 = __floats2half2_rn(o[2], o[3]);
    __half2 q2 = __floats2half2_rn(o[4], o[5]);
    __half2 q3 = __floats2half2_rn(o[6], o[7]);
    uint4 u = make_uint4(*(uint32_t*)&q0, *(uint32_t*)&q1, *(uint32_t*)&q2, *(uint32_t*)&q3);
    *(uint4*)&g[base + (s1_0 + r) * 128 + cb] = u;
}

// ---------------- fp16 tensor-core implicit-GEMM 3x3 conv ----------------
// OUTH: 0 fp32 planar (+RES), 1 half2 pair-interleaved (PERM), 2 half planar
template<int C, int S1, int W, int OUTV, int RES, int OUTH>
__global__ __launch_bounds__(256, 2)
void conv3x3_f16(const uint32_t* __restrict__ xh2, const __half* __restrict__ wprep,
                 const float* __restrict__ bias, void* __restrict__ outv,
                 const float* __restrict__ res,
                 int o_oc, int o_s1, int o_s2, int o_b)
{
    constexpr int TR = 256 / W;
    constexpr int NS = C / 16;
    constexpr int RW = W + 8;
    constexpr int SK = (TR + 2) * RW + 8;
    constexpr int ASLAB = 9 * 512;
    constexpr int BSLAB = 8 * SK;
    constexpr int BCH = W / 4;

    extern __shared__ uint32_t smu[];
    uint32_t* wsm = smu;
    uint32_t* bsm = smu + 2 * ASLAB;

    const int tid = threadIdx.x;
    const int s1_0 = blockIdx.x * TR;
    const int oc0 = blockIdx.y * 64;
    const int b = blockIdx.z;
    const uint32_t* xb = xh2 + b * ((C / 2) * S1 * W);
    const __half* wsrc = wprep + blockIdx.y * (NS * 9216);

    for (int i = tid; i < 2 * 8 * (TR + 2) * 2; i += 256) {
        int side = i & 1; int rest = i >> 1;
        int row = rest % (TR + 2); rest /= (TR + 2);
        int kp = rest & 7; int bufi = rest >> 3;
        bsm[bufi * BSLAB + kp * SK + row * RW + (side ? (W + 4) : 3)] = 0u;
    }

    auto stageA = [&](int slab, int bufi) {
        uint32_t d0 = (uint32_t)__cvta_generic_to_shared(wsm + bufi * ASLAB);
        const __half* src = wsrc + slab * 9216;
        for (int i = tid; i < 1152; i += 256)
            cp_async16(d0 + (uint32_t)(i * 16), src + i * 8, true);
    };
    auto stageB = [&](int slab, int bufi) {
        uint32_t d0 = (uint32_t)__cvta_generic_to_shared(bsm + bufi * BSLAB);
        const uint32_t* src = xb + slab * 8 * (S1 * W);
        for (int i = tid; i < 8 * (TR + 2) * BCH; i += 256) {
            int j = i % BCH; int rest = i / BCH;
            int row = rest % (TR + 2); int kp = rest / (TR + 2);
            int s1g = s1_0 - 1 + row;
            bool v = (s1g >= 0) && (s1g < S1);
            int s1c = v ? s1g : 0;
            cp_async16(d0 + (uint32_t)((kp * SK + row * RW + 4 + 4 * j) * 4),
                       src + kp * (S1 * W) + s1c * W + 4 * j, v);
        }
    };

    stageA(0, 0); stageB(0, 0); cp_commit();

    const int lane = tid & 31, warp = tid >> 5;
    const int g = lane >> 2, tq = lane & 3;
    const int rbase = (warp * 32) / W;
    const int cb0 = (warp * 32) % W;
    const int afrag = lane * 4;

    float acc[4][4][4];
#pragma unroll
    for (int mt = 0; mt < 4; mt++)
#pragma unroll
        for (int nt = 0; nt < 4; nt++)
#pragma unroll
            for (int q = 0; q < 4; q++) acc[mt][nt][q] = 0.f;

    int buf = 0;
    for (int slab = 0; slab < NS; slab++) {
        cp_wait0();
        __syncthreads();
        if (slab + 1 < NS) { stageA(slab + 1, buf ^ 1); stageB(slab + 1, buf ^ 1); cp_commit(); }

        const uint32_t* wa = wsm + buf * ASLAB;
        const uint32_t* bb = bsm + buf * BSLAB;
#pragma unroll
        for (int dr = 0; dr < 3; dr++) {
#pragma unroll
            for (int dc = 0; dc < 3; dc++) {
                const int s = dr * 3 + dc;
                uint4 au4[4];
                const uint32_t* wp = &wa[s * 512 + afrag];
#pragma unroll
                for (int mt = 0; mt < 4; mt++)
                    au4[mt] = *(const uint4*)&wp[mt * 128];
                int bbase = tq * SK + (rbase + dr) * RW + cb0 + g + dc + 3;
#pragma unroll
                for (int nt = 0; nt < 4; nt++) {
                    uint32_t b0 = bb[bbase + 8 * nt];
                    uint32_t b1 = bb[bbase + 4 * SK + 8 * nt];
#pragma unroll
                    for (int mt = 0; mt < 4; mt++)
                        mma_f16(acc[mt][nt], (const uint32_t*)&au4[mt], b0, b1);
                }
            }
        }
        buf ^= 1;
    }

    const int s1 = s1_0 + rbase;
    if (OUTH == 1) {
        uint32_t* outp = (uint32_t*)outv;
#pragma unroll
        for (int mt = 0; mt < 4; mt++) {
            const int ocb16 = oc0 + 16 * mt;
            const float bve = bias[ocb16 + 2 * g];
            const float bvo = bias[ocb16 + 2 * g + 1];
            const int ocp = (ocb16 >> 1) + g;
#pragma unroll
            for (int nt = 0; nt < 4; nt++) {
                const int px = cb0 + 8 * nt + 2 * tq;
                float v0 = lrelu(acc[mt][nt][0] + bve);
                float v1 = lrelu(acc[mt][nt][1] + bve);
                float v2 = lrelu(acc[mt][nt][2] + bvo);
                float v3 = lrelu(acc[mt][nt][3] + bvo);
                __half2 h0 = __floats2half2_rn(v0, v2);
                __half2 h1 = __floats2half2_rn(v1, v3);
                int e = b * o_b + ocp * o_oc + s1 * o_s1 + px;
                *(uint2*)&outp[e] = make_uint2(*(uint32_t*)&h0, *(uint32_t*)&h1);
            }
        }
    } else if (OUTH == 2) {
        __half* outh = (__half*)outv;
#pragma unroll
        for (int mt = 0; mt < 4; mt++) {
            const int oc = oc0 + 16 * mt + g;
            const float bv0 = bias[oc], bv1 = bias[oc + 8];
#pragma unroll
            for (int nt = 0; nt < 4; nt++) {
                const int pc = cb0 + 8 * nt + 2 * tq;
                float v0 = lrelu(acc[mt][nt][0] + bv0);
                float v1 = lrelu(acc[mt][nt][1] + bv0);
                float v2 = lrelu(acc[mt][nt][2] + bv1);
                float v3 = lrelu(acc[mt][nt][3] + bv1);
                if (OUTV == 0) {
                    int e0 = b * o_b + oc * o_oc + s1 * o_s1 + pc;
                    int e1 = e0 + 8 * o_oc;
                    *(__half2*)&outh[e0] = __floats2half2_rn(v0, v1);
                    *(__half2*)&outh[e1] = __floats2half2_rn(v2, v3);
                } else {
                    int e = b * o_b + s1 * o_s1 + oc;
                    outh[e + pc * o_s2] = __float2half_rn(v0);
                    outh[e + (pc + 1) * o_s2] = __float2half_rn(v1);
                    outh[e + 8 + pc * o_s2] = __float2half_rn(v2);
                    outh[e + 8 + (pc + 1) * o_s2] = __float2half_rn(v3);
                }
            }
        }
    } else {
        float* out = (float*)outv;
#pragma unroll
        for (int mt = 0; mt < 4; mt++) {
            const int oc = oc0 + 16 * mt + g;
            const float bv0 = bias[oc], bv1 = bias[oc + 8];
#pragma unroll
            for (int nt = 0; nt < 4; nt++) {
                const int pc = cb0 + 8 * nt + 2 * tq;
                float v0 = lrelu(acc[mt][nt][0] + bv0);
                float v1 = lrelu(acc[mt][nt][1] + bv0);
                float v2 = lrelu(acc[mt][nt][2] + bv1);
                float v3 = lrelu(acc[mt][nt][3] + bv1);
                int e0 = b * o_b + oc * o_oc + s1 * o_s1 + pc;
                int e1 = e0 + 8 * o_oc;
                if (RES) {
                    v0 += res[e0]; v1 += res[e0 + 1];
                    v2 += res[e1]; v3 += res[e1 + 1];
                }
                *(float2*)&out[e0] = make_float2(v0, v1);
                *(float2*)&out[e1] = make_float2(v2, v3);
            }
        }
    }
}

// ---------------- down-GEMM ----------------
__global__ __launch_bounds__(256)
void gemm_down_f16(const uint32_t* __restrict__ xr, const __half* __restrict__ g,
                   const __half* __restrict__ xhw, const __half* __restrict__ xcw,
                   const __half* __restrict__ xhc, const __half* __restrict__ wdf,
                   const float* __restrict__ b_down, uint32_t* __restrict__ midh2)
{
    constexpr int SKB = 264;
    __shared__ __align__(16) uint32_t asmem[16 * 512];
    __shared__ __align__(16) uint32_t bsm[2 * 8 * SKB];

    const int tid = threadIdx.x;
    const int p0 = blockIdx.x * 256;
    const int b = blockIdx.z;

    {
        uint32_t dA = (uint32_t)__cvta_generic_to_shared(asmem);
        for (int i = tid; i < 2048; i += 256)
            cp_async16(dA + (uint32_t)(i * 16), wdf + i * 8, true);
        cp_commit();
    }

    const int lane = tid & 31, warp = tid >> 5;
    const int gq = lane >> 2, tq = lane & 3;
    const int cb0 = warp * 32;

    const int kp = tid >> 5;
    const int pxc = (tid & 31) * 8;
    const int pxg = p0 + pxc;

    uint4 r0, r1, r2, r3;

    auto loadRegs = [&](int s) {
        if (s < 4) {
            const uint32_t* src = xr + (b * 32 + s * 8 + kp) * HW_ + pxg;
            r0 = *(const uint4*)src;
            r1 = *(const uint4*)(src + 4);
        } else {
            int s4 = s - 4;
            int gc = 16 * s4 + 2 * kp;
            const __half* gp0 = g + (b * 192 + gc) * HW_ + pxg;
            const __half* br = (s4 < 4) ? xhw : ((s4 < 8) ? xcw : xhc);
            int bc = (s4 & 3) * 16 + 2 * kp;
            const __half* bp0 = br + (b * 64 + bc) * HW_ + pxg;
            r0 = *(const uint4*)gp0;
            r1 = *(const uint4*)(gp0 + HW_);
            r2 = *(const uint4*)bp0;
            r3 = *(const uint4*)(bp0 + HW_);
        }
    };
    auto stsRegs = [&](int s, int bufi) {
        uint32_t* dst = bsm + bufi * (8 * SKB) + kp * SKB + pxc;
        if (s < 4) {
            *(uint4*)dst = r0;
            *(uint4*)(dst + 4) = r1;
        } else {
            const __half* G0 = (const __half*)&r0;
            const __half* G1 = (const __half*)&r1;
            const __half* B0 = (const __half*)&r2;
            const __half* B1 = (const __half*)&r3;
            uint32_t o[8];
#pragma unroll
            for (int j = 0; j < 8; j++) {
                __half2 h = __floats2half2_rn(
                    __half2float(G0[j]) * __half2float(B0[j]),
                    __half2float(G1[j]) * __half2float(B1[j]));
                o[j] = *(uint32_t*)&h;
            }
            *(uint4*)dst = make_uint4(o[0], o[1], o[2], o[3]);
            *(uint4*)(dst + 4) = make_uint4(o[4], o[5], o[6], o[7]);
        }
    };

    float acc[4][4][4];
#pragma unroll
    for (int mt = 0; mt < 4; mt++)
#pragma unroll
        for (int nt = 0; nt < 4; nt++)
#pragma unroll
            for (int q = 0; q < 4; q++) acc[mt][nt][q] = 0.f;

    cp_wait0();
    loadRegs(0);
    stsRegs(0, 0);
    __syncthreads();

    int buf = 0;
    for (int s = 0; s < 16; s++) {
        if (s + 1 < 16) loadRegs(s + 1);
        const uint32_t* wa = asmem + s * 512;
        uint4 au4[4];
#pragma unroll
        for (int mt = 0; mt < 4; mt++)
            au4[mt] = *(const uint4*)&wa[mt * 128 + lane * 4];
        const uint32_t* bb = bsm + buf * (8 * SKB);
        int bbase = tq * SKB + cb0 + gq;
#pragma unroll
        for (int nt = 0; nt < 4; nt++) {
            uint32_t b0 = bb[bbase + 8 * nt];
            uint32_t b1 = bb[bbase + 4 * SKB + 8 * nt];
#pragma unroll
            for (int mt = 0; mt < 4; mt++)
                mma_f16(acc[mt][nt], (const uint32_t*)&au4[mt], b0, b1);
        }
        if (s + 1 < 16) {
            stsRegs(s + 1, buf ^ 1);
            __syncthreads();
        }
        buf ^= 1;
    }

#pragma unroll
    for (int mt = 0; mt < 4; mt++) {
        const float be = b_down[16 * mt + 2 * gq];
        const float bo = b_down[16 * mt + 2 * gq + 1];
        const int ocp = 8 * mt + gq;
#pragma unroll
        for (int nt = 0; nt < 4; nt++) {
            const int pc = p0 + cb0 + 8 * nt + 2 * tq;
            uint2 xres = *(const uint2*)&xr[(b * 32 + ocp) * HW_ + pc];
            float2 xa = __half22float2(*(__half2*)&xres.x);
            float2 xb2 = __half22float2(*(__half2*)&xres.y);
            float v0 = acc[mt][nt][0] + be + xa.x;
            float v2 = acc[mt][nt][2] + bo + xa.y;
            float v1 = acc[mt][nt][1] + be + xb2.x;
            float v3 = acc[mt][nt][3] + bo + xb2.y;
            __half2 m0 = __floats2half2_rn(v0, v2);
            __half2 m1 = __floats2half2_rn(v1, v3);
            *(uint2*)&midh2[(b * 32 + ocp) * HW_ + pc] =
                make_uint2(*(uint32_t*)&m0, *(uint32_t*)&m1);
        }
    }
}

// ---------------- stream/event pool ----------------
struct AsyncCtx {
    cudaStream_t s1, s2, s3;
    cudaEvent_t eRoot, eR4, eCw, eHc, eHw, eG, eT1;
    bool ok;
    AsyncCtx() {
        ok = true;
        ok &= (cudaStreamCreateWithFlags(&s1, cudaStreamNonBlocking) == cudaSuccess);
        ok &= (cudaStreamCreateWithFlags(&s2, cudaStreamNonBlocking) == cudaSuccess);
        ok &= (cudaStreamCreateWithFlags(&s3, cudaStreamNonBlocking) == cudaSuccess);
        ok &= (cudaEventCreateWithFlags(&eRoot, cudaEventDisableTiming) == cudaSuccess);
        ok &= (cudaEventCreateWithFlags(&eR4, cudaEventDisableTiming) == cudaSuccess);
        ok &= (cudaEventCreateWithFlags(&eCw, cudaEventDisableTiming) == cudaSuccess);
        ok &= (cudaEventCreateWithFlags(&eHc, cudaEventDisableTiming) == cudaSuccess);
        ok &= (cudaEventCreateWithFlags(&eHw, cudaEventDisableTiming) == cudaSuccess);
        ok &= (cudaEventCreateWithFlags(&eG, cudaEventDisableTiming) == cudaSuccess);
        ok &= (cudaEventCreateWithFlags(&eT1, cudaEventDisableTiming) == cudaSuccess);
    }
};

// ---------------- launch ----------------
extern "C" void kernel_launch(void* const* d_in, const int* in_sizes, int n_in,
                              void* d_out, int out_size)
{
    const float* x      = (const float*)d_in[0];
    const float* w_hwc  = (const float*)d_in[1];
    const float* b_hwc  = (const float*)d_in[2];
    const float* w_dw   = (const float*)d_in[3];
    const float* b_dw   = (const float*)d_in[4];
    const float* w_hw   = (const float*)d_in[5];
    const float* b_hw   = (const float*)d_in[6];
    const float* w_cw   = (const float*)d_in[7];
    const float* b_cw   = (const float*)d_in[8];
    const float* w_hc   = (const float*)d_in[9];
    const float* b_hc   = (const float*)d_in[10];
    const float* w_down = (const float*)d_in[11];
    const float* b_down = (const float*)d_in[12];
    const float* w_l1   = (const float*)d_in[13];
    const float* b_l1   = (const float*)d_in[14];
    const float* w_l2   = (const float*)d_in[15];
    const float* b_l2   = (const float*)d_in[16];
    float* out = (float*)d_out;

    __half *t, *g, *xhw, *xcw, *xhc;
    uint32_t *xt1, *xt2, *xr, *mid, *o1;
    __half *wrh, *w1h, *wdfh;
    { void* p;
      cudaGetSymbolAddress(&p, d_t);   t   = (__half*)p;
      cudaGetSymbolAddress(&p, d_g);   g   = (__half*)p;
      cudaGetSymbolAddress(&p, d_xt1); xt1 = (uint32_t*)p;
      cudaGetSymbolAddress(&p, d_xt2); xt2 = (uint32_t*)p;
      cudaGetSymbolAddress(&p, d_xr);  xr  = (uint32_t*)p;
      cudaGetSymbolAddress(&p, d_xhw); xhw = (__half*)p;
      cudaGetSymbolAddress(&p, d_xcw); xcw = (__half*)p;
      cudaGetSymbolAddress(&p, d_xhc); xhc = (__half*)p;
      cudaGetSymbolAddress(&p, d_mid); mid = (uint32_t*)p;
      cudaGetSymbolAddress(&p, d_o1);  o1  = (uint32_t*)p;
      cudaGetSymbolAddress(&p, d_wr);  wrh = (__half*)p;
      cudaGetSymbolAddress(&p, d_w1);  w1h = (__half*)p;
      cudaGetSymbolAddress(&p, d_wdf); wdfh = (__half*)p;
    }

    __half* wf_hw = wrh;
    __half* wf_cw = wrh + 36864;
    __half* wf_hc = wrh + 184320;
    __half* wf_l1 = wrh + 331776;
    __half* wf_l2 = wrh + 368640;

    const int SM128 = (2 * 4608 + 2 * (8 * ((2 + 2) * 136 + 8))) * 4;  // 72192
    const int SM64  = (2 * 4608 + 2 * (8 * ((4 + 2) * 72 + 8))) * 4;   // 65024

    cudaFuncSetAttribute((const void*)conv3x3_f16<64, 128, 128, 0, 0, 2>,
                         cudaFuncAttributeMaxDynamicSharedMemorySize, SM128);
    cudaFuncSetAttribute((const void*)conv3x3_f16<128, 64, 128, 0, 0, 2>,
                         cudaFuncAttributeMaxDynamicSharedMemorySize, SM128);
    cudaFuncSetAttribute((const void*)conv3x3_f16<128, 128, 64, 1, 0, 2>,
                         cudaFuncAttributeMaxDynamicSharedMemorySize, SM64);
    cudaFuncSetAttribute((const void*)conv3x3_f16<64, 128, 128, 0, 0, 1>,
                         cudaFuncAttributeMaxDynamicSharedMemorySize, SM128);
    cudaFuncSetAttribute((const void*)conv3x3_f16<64, 128, 128, 0, 1, 0>,
                         cudaFuncAttributeMaxDynamicSharedMemorySize, SM128);

    static AsyncCtx ctx;

    // batch-half offsets (elements)
    const int HB = 4;
    const size_t oXR = (size_t)HB * 32 * HW_;   // xr/mid/o1 (u32)
    const size_t oT  = (size_t)HB * GBS_;       // t/g (half)
    const size_t oBR = (size_t)HB * CHW_;       // branches (half) / x,out (float)

    if (ctx.ok) {
        cudaStream_t m = 0;
        cudaEventRecord(ctx.eRoot, m);
        cudaStreamWaitEvent(ctx.s1, ctx.eRoot, 0);
        cudaStreamWaitEvent(ctx.s2, ctx.eRoot, 0);
        cudaStreamWaitEvent(ctx.s3, ctx.eRoot, 0);

        // main: w1 prep + merged xr/xt1 prep
        prep_w1f_kernel<<<48, 256, 0, m>>>(w_hwc, w1h);
        pt1_kernel<<<2048, 256, 0, m>>>(x, xr, xt1);
        cudaEventRecord(ctx.eR4, m);

        // s1: cw branch
        prep_wf_kernel<<<576, 256, 0, ctx.s1>>>(w_cw, wf_cw, 128, 128, 0);
        cudaStreamWaitEvent(ctx.s1, ctx.eR4, 0);
        conv3x3_f16<128, 64, 128, 0, 0, 2><<<dim3(32, 2, 8), 256, SM128, ctx.s1>>>(
            xt1, wf_cw, b_cw, xcw, nullptr, 128, HW_, 1, CHW_);
        cudaEventRecord(ctx.eCw, ctx.s1);

        // s2: hc branch
        prep_wf_kernel<<<576, 256, 0, ctx.s2>>>(w_hc, wf_hc, 128, 128, 0);
        t2f_kernel<<<dim3(4, 2, 1024), dim3(32, 8), 0, ctx.s2>>>(x, xt2);
        conv3x3_f16<128, 128, 64, 1, 0, 2><<<dim3(32, 2, 8), 256, SM64, ctx.s2>>>(
            xt2, wf_hc, b_hc, xhc, nullptr, 1, 128, HW_, CHW_);
        cudaEventRecord(ctx.eHc, ctx.s2);

        // s3: hw branch + misc preps
        prep_wf_kernel<<<144, 256, 0, ctx.s3>>>(w_hw, wf_hw, 64, 64, 0);
        prep_wdf_kernel<<<64, 256, 0, ctx.s3>>>(w_down, wdfh);
        prep_wf_kernel<<<144, 256, 0, ctx.s3>>>(w_l1, wf_l1, 64, 64, 1);
        prep_wf_kernel<<<144, 256, 0, ctx.s3>>>(w_l2, wf_l2, 64, 64, 0);
        cudaStreamWaitEvent(ctx.s3, ctx.eR4, 0);
        conv3x3_f16<64, 128, 128, 0, 0, 2><<<dim3(64, 1, 8), 256, SM128, ctx.s3>>>(
            xr, wf_hw, b_hw, xhw, nullptr, HW_, 128, 1, CHW_);
        cudaEventRecord(ctx.eHw, ctx.s3);

        // main: gate path (full batch)
        gemm1x1_f16<<<dim3(64, 3, 8), 256, 0, m>>>(xr, w1h, b_hwc, t);
        dwconv_v3_kernel<<<dim3(8, 192, 8), 256, 0, m>>>(t, w_dw, b_dw, g);
        cudaEventRecord(ctx.eG, m);

        // joins for chain 0 on m
        cudaStreamWaitEvent(m, ctx.eCw, 0);
        cudaStreamWaitEvent(m, ctx.eHc, 0);
        cudaStreamWaitEvent(m, ctx.eHw, 0);

        // joins for chain 1 on s1 (eCw implicit by stream order)
        cudaStreamWaitEvent(ctx.s1, ctx.eG, 0);
        cudaStreamWaitEvent(ctx.s1, ctx.eHc, 0);
        cudaStreamWaitEvent(ctx.s1, ctx.eHw, 0);

        // chain 0 tail (b0-3) on m
        gemm_down_f16<<<dim3(64, 1, HB), 256, 0, m>>>(xr, g, xhw, xcw, xhc, wdfh, b_down, mid);
        conv3x3_f16<64, 128, 128, 0, 0, 1><<<dim3(64, 1, HB), 256, SM128, m>>>(
            mid, wf_l1, b_l1, o1, nullptr, HW_, 128, 1, 32 * HW_);
        conv3x3_f16<64, 128, 128, 0, 1, 0><<<dim3(64, 1, HB), 256, SM128, m>>>(
            o1, wf_l2, b_l2, out, x, HW_, 128, 1, CHW_);

        // chain 1 tail (b4-7) on s1
        gemm_down_f16<<<dim3(64, 1, HB), 256, 0, ctx.s1>>>(
            xr + oXR, g + oT, xhw + oBR, xcw + oBR, xhc + oBR, wdfh, b_down, mid + oXR);
        conv3x3_f16<64, 128, 128, 0, 0, 1><<<dim3(64, 1, HB), 256, SM128, ctx.s1>>>(
            mid + oXR, wf_l1, b_l1, o1 + oXR, nullptr, HW_, 128, 1, 32 * HW_);
        conv3x3_f16<64, 128, 128, 0, 1, 0><<<dim3(64, 1, HB), 256, SM128, ctx.s1>>>(
            o1 + oXR, wf_l2, b_l2, out + oBR, x + oBR, HW_, 128, 1, CHW_);
        cudaEventRecord(ctx.eT1, ctx.s1);
        cudaStreamWaitEvent(m, ctx.eT1, 0);
    } else {
        // serial fallback
        prep_wf_kernel<<<144, 256>>>(w_hw, wf_hw, 64, 64, 0);
        prep_wf_kernel<<<576, 256>>>(w_cw, wf_cw, 128, 128, 0);
        prep_wf_kernel<<<576, 256>>>(w_hc, wf_hc, 128, 128, 0);
        prep_wf_kernel<<<144, 256>>>(w_l1, wf_l1, 64, 64, 1);
        prep_wf_kernel<<<144, 256>>>(w_l2, wf_l2, 64, 64, 0);
        prep_w1f_kernel<<<48, 256>>>(w_hwc, w1h);
        prep_wdf_kernel<<<64, 256>>>(w_down, wdfh);
        pt1_kernel<<<2048, 256>>>(x, xr, xt1);
        t2f_kernel<<<dim3(4, 2, 1024), dim3(32, 8)>>>(x, xt2);
        gemm1x1_f16<<<dim3(64, 3, 8), 256>>>(xr, w1h, b_hwc, t);
        dwconv_v3_kernel<<<dim3(8, 192, 8), 256>>>(t, w_dw, b_dw, g);
        conv3x3_f16<64, 128, 128, 0, 0, 2><<<dim3(64, 1, 8), 256, SM128>>>(
            xr, wf_hw, b_hw, xhw, nullptr, HW_, 128, 1, CHW_);
        conv3x3_f16<128, 64, 128, 0, 0, 2><<<dim3(32, 2, 8), 256, SM128>>>(
            xt1, wf_cw, b_cw, xcw, nullptr, 128, HW_, 1, CHW_);
        conv3x3_f16<128, 128, 64, 1, 0, 2><<<dim3(32, 2, 8), 256, SM64>>>(
            xt2, wf_hc, b_hc, xhc, nullptr, 1, 128, HW_, CHW_);
        gemm_down_f16<<<dim3(64, 1, 8), 256>>>(xr, g, xhw, xcw, xhc, wdfh, b_down, mid);
        conv3x3_f16<64, 128, 128, 0, 0, 1><<<dim3(64, 1, 8), 256, SM128>>>(
            mid, wf_l1, b_l1, o1, nullptr, HW_, 128, 1, 32 * HW_);
        conv3x3_f16<64, 128, 128, 0, 1, 0><<<dim3(64, 1, 8), 256, SM128>>>(
            o1, wf_l2, b_l2, out, x, HW_, 128, 1, CHW_);
    }
}

// round 17
// speedup vs baseline: 1.0772x; 1.0238x over previous
#include <cuda_runtime.h>
#include <cuda_fp16.h>
#include <cstdint>

// B=8, C=64, T=128
#define HW_   16384
#define CHW_  1048576
#define GBS_  3145728

typedef unsigned long long ull;

// ---------------- scratch ----------------
__device__ float d_t  [12582912];  // half [8,192,128,128] conv1x1 out
__device__ float d_g  [12582912];  // half [8,192,128,128] gates (planar)
__device__ float d_xt1[8388608];   // half2 [b][h/2][c][w]
__device__ float d_xt2[8388608];   // half2 [b][w/2][h][c]
__device__ float d_xr [8388608];   // half2 [b][c/2][h][w]
__device__ float d_xhw[4194304];   // half planar [b][c][h][w]
__device__ float d_xcw[4194304];
__device__ float d_xhc[4194304];
__device__ float d_mid[8388608];   // half2 [b][c/2][h][w]
__device__ float d_o1 [8388608];   // half2 [b][c/2][h][w]
__device__ float d_wr [405504];    // fp16 conv weights (lane-fragment order)
__device__ float d_w1 [12288];     // fp16 1x1 weights
__device__ float d_wdf[8192];      // fp16 down-GEMM weights

__device__ __forceinline__ float lrelu(float v) { return v > 0.f ? v : 0.1f * v; }

__device__ __forceinline__ void cp_async16(uint32_t dst, const void* src, bool valid) {
    int sz = valid ? 16 : 0;
    asm volatile("cp.async.cg.shared.global [%0], [%1], 16, %2;\n"
                 :: "r"(dst), "l"(src), "r"(sz));
}
__device__ __forceinline__ void cp_commit() { asm volatile("cp.async.commit_group;\n"); }
__device__ __forceinline__ void cp_wait0()  { asm volatile("cp.async.wait_group 0;\n"); }

__device__ __forceinline__ float4 h4_to_f4(uint2 u) {
    float2 a = __half22float2(*(__half2*)&u.x);
    float2 b = __half22float2(*(__half2*)&u.y);
    return make_float4(a.x, a.y, b.x, b.y);
}

// ---------------- fp16 mma (m16n8k16, fp32 accum) ----------------
__device__ __forceinline__ void mma_f16(float* d, const uint32_t* a,
                                        uint32_t b0, uint32_t b1) {
    asm volatile("mma.sync.aligned.m16n8k16.row.col.f32.f16.f16.f32 "
                 "{%0,%1,%2,%3}, {%4,%5,%6,%7}, {%8,%9}, {%0,%1,%2,%3};"
                 : "+f"(d[0]), "+f"(d[1]), "+f"(d[2]), "+f"(d[3])
                 : "r"(a[0]), "r"(a[1]), "r"(a[2]), "r"(a[3]), "r"(b0), "r"(b1));
}

// ---------------- prep kernels (lane-fragment order) ----------------
__global__ void prep_wf_kernel(const float* __restrict__ src, __half* __restrict__ dst,
                               int OC, int C, int PERM)
{
    int idx = blockIdx.x * 256 + threadIdx.x;
    int total = OC * C * 9;
    if (idx >= total) return;
    int klo  = idx & 1;
    int q    = (idx >> 1) & 3;
    int lane = (idx >> 3) & 31;
    int mt   = (idx >> 8) & 3;
    int s    = (idx >> 10) % 9;
    int rest = idx / 9216;
    int NS = C >> 4;
    int slab = rest % NS;
    int ocb = rest / NS;
    int g = lane >> 2, tq = lane & 3;
    int oc_l = 16 * mt + 8 * (q & 1) + g;
    if (PERM) {
        int grp = oc_l >> 4, r = oc_l & 15;
        oc_l = grp * 16 + ((r < 8) ? 2 * r : 2 * (r - 8) + 1);
    }
    int k = slab * 16 + 2 * (tq + 4 * (q >> 1)) + klo;
    dst[idx] = __float2half_rn(src[((ocb * 64 + oc_l) * C + k) * 9 + s]);
}

__global__ void prep_w1f_kernel(const float* __restrict__ src, __half* __restrict__ dst)
{
    int idx = blockIdx.x * 256 + threadIdx.x;
    if (idx >= 12288) return;
    int klo  = idx & 1;
    int q    = (idx >> 1) & 3;
    int lane = (idx >> 3) & 31;
    int mt   = (idx >> 8) & 3;
    int slab = (idx >> 10) & 3;
    int ocb  = idx >> 12;
    int g = lane >> 2, tq = lane & 3;
    int oc_l = 16 * mt + 8 * (q & 1) + g;
    int k = slab * 16 + 2 * (tq + 4 * (q >> 1)) + klo;
    dst[idx] = __float2half_rn(src[(ocb * 64 + oc_l) * 64 + k]);
}

__global__ void prep_wdf_kernel(const float* __restrict__ w_down, __half* __restrict__ dst)
{
    int idx = blockIdx.x * 256 + threadIdx.x;
    if (idx >= 16384) return;
    int klo  = idx & 1;
    int q    = (idx >> 1) & 3;
    int lane = (idx >> 3) & 31;
    int mt   = (idx >> 8) & 3;
    int slab = idx >> 10;
    int g = lane >> 2, tq = lane & 3;
    int oc_l = 16 * mt + 8 * (q & 1) + g;
    {
        int grp = oc_l >> 4, r = oc_l & 15;
        oc_l = grp * 16 + ((r < 8) ? 2 * r : 2 * (r - 8) + 1);
    }
    int k = slab * 16 + 2 * (tq + 4 * (q >> 1)) + klo;
    int s = k >> 6;
    int c = k & 63;
    auto W = [&](int i, int ky, int kx) { return w_down[((oc_l * 128 + i) * 2 + ky) * 2 + kx]; };
    float v;
    if (s == 0)      v = W(2 * c, 0, 0) + W(2 * c + 1, 1, 1);
    else if (s == 1) v = W(2 * c, 0, 1) + W(2 * c + 1, 1, 0);
    else if (s == 2) v = W(2 * c, 1, 0) + W(2 * c + 1, 0, 1);
    else             v = W(2 * c, 1, 1) + W(2 * c + 1, 0, 0);
    dst[idx] = __float2half_rn(v);
}

// ---------------- merged x -> (xr pair-interleave, xt1 row-pair) ----------------
__global__ __launch_bounds__(256)
void pt1_kernel(const float* __restrict__ x, uint32_t* __restrict__ xr,
                uint32_t* __restrict__ xt1)
{
    int i = blockIdx.x * 256 + threadIdx.x;
    int w4 = i & 31;
    int hp = (i >> 5) & 63;
    int cp = (i >> 11) & 31;
    int b  = i >> 16;
    const float* pl0 = x + (b * 64 + 2 * cp) * HW_;
    const float* pl1 = pl0 + HW_;
    float4 a0 = *(const float4*)&pl0[(2 * hp) * 128 + 4 * w4];
    float4 a1 = *(const float4*)&pl0[(2 * hp + 1) * 128 + 4 * w4];
    float4 c0 = *(const float4*)&pl1[(2 * hp) * 128 + 4 * w4];
    float4 c1 = *(const float4*)&pl1[(2 * hp + 1) * 128 + 4 * w4];

    {
        __half2 h0 = __floats2half2_rn(a0.x, c0.x);
        __half2 h1 = __floats2half2_rn(a0.y, c0.y);
        __half2 h2 = __floats2half2_rn(a0.z, c0.z);
        __half2 h3 = __floats2half2_rn(a0.w, c0.w);
        *(uint4*)&xr[(b * 32 + cp) * HW_ + (2 * hp) * 128 + 4 * w4] =
            make_uint4(*(uint32_t*)&h0, *(uint32_t*)&h1, *(uint32_t*)&h2, *(uint32_t*)&h3);
        __half2 k0 = __floats2half2_rn(a1.x, c1.x);
        __half2 k1 = __floats2half2_rn(a1.y, c1.y);
        __half2 k2 = __floats2half2_rn(a1.z, c1.z);
        __half2 k3 = __floats2half2_rn(a1.w, c1.w);
        *(uint4*)&xr[(b * 32 + cp) * HW_ + (2 * hp + 1) * 128 + 4 * w4] =
            make_uint4(*(uint32_t*)&k0, *(uint32_t*)&k1, *(uint32_t*)&k2, *(uint32_t*)&k3);
    }
    {
        __half2 h0 = __floats2half2_rn(a0.x, a1.x);
        __half2 h1 = __floats2half2_rn(a0.y, a1.y);
        __half2 h2 = __floats2half2_rn(a0.z, a1.z);
        __half2 h3 = __floats2half2_rn(a0.w, a1.w);
        *(uint4*)&xt1[((b * 64 + hp) * 64 + 2 * cp) * 128 + 4 * w4] =
            make_uint4(*(uint32_t*)&h0, *(uint32_t*)&h1, *(uint32_t*)&h2, *(uint32_t*)&h3);
        __half2 k0 = __floats2half2_rn(c0.x, c1.x);
        __half2 k1 = __floats2half2_rn(c0.y, c1.y);
        __half2 k2 = __floats2half2_rn(c0.z, c1.z);
        __half2 k3 = __floats2half2_rn(c0.w, c1.w);
        *(uint4*)&xt1[((b * 64 + hp) * 64 + 2 * cp + 1) * 128 + 4 * w4] =
            make_uint4(*(uint32_t*)&k0, *(uint32_t*)&k1, *(uint32_t*)&k2, *(uint32_t*)&k3);
    }
}

// ---------------- t2: half2 [b][w/2][h][c] ----------------
__global__ __launch_bounds__(256)
void t2f_kernel(const float* __restrict__ x, uint32_t* __restrict__ o)
{
    __shared__ float tile[32][33];
    int tx = threadIdx.x, ty = threadIdx.y;
    int w0 = blockIdx.x * 32;
    int c0 = blockIdx.y * 32;
    int bh = blockIdx.z;
    int b = bh >> 7, hrow = bh & 127;
    int xb = b * CHW_ + hrow * 128;
#pragma unroll
    for (int i = 0; i < 4; i++)
        tile[ty + 8 * i][tx] = x[xb + (c0 + ty + 8 * i) * HW_ + w0 + tx];
    __syncthreads();
#pragma unroll
    for (int j = 0; j < 2; j++) {
        int wl = ty + 8 * j;
        __half2 hv = __floats2half2_rn(tile[tx][2 * wl], tile[tx][2 * wl + 1]);
        o[((b * 64 + (w0 >> 1) + wl) * 128 + hrow) * 64 + c0 + tx] = *(uint32_t*)&hv;
    }
}

// ---------------- conv1x1 via fp16 MMA ----------------
__global__ __launch_bounds__(256)
void gemm1x1_f16(const uint32_t* __restrict__ xh2, const __half* __restrict__ wprep,
                 const float* __restrict__ bias, __half* __restrict__ t)
{
    constexpr int SKB = 264;
    constexpr int ASLAB = 512;
    constexpr int BSLAB = 8 * SKB;
    __shared__ __align__(16) uint32_t sm[2 * (ASLAB + BSLAB)];
    uint32_t* wsm = sm;
    uint32_t* bsm = sm + 2 * ASLAB;

    const int tid = threadIdx.x;
    const int p0 = blockIdx.x * 256;
    const int oc0 = blockIdx.y * 64;
    const int b = blockIdx.z;
    const __half* wsrc = wprep + blockIdx.y * 4096;
    const uint32_t* xsrc = xh2 + b * (32 * HW_) + p0;

    auto stage = [&](int slab, int bufi) {
        uint32_t dA = (uint32_t)__cvta_generic_to_shared(wsm + bufi * ASLAB);
        uint32_t dB = (uint32_t)__cvta_generic_to_shared(bsm + bufi * BSLAB);
        const __half* sA = wsrc + slab * 1024;
        for (int i = tid; i < 128; i += 256)
            cp_async16(dA + (uint32_t)(i * 16), sA + i * 8, true);
        for (int i = tid; i < 512; i += 256) {
            int kp = i >> 6, j = i & 63;
            cp_async16(dB + (uint32_t)((kp * SKB + 4 * j) * 4),
                       xsrc + (slab * 8 + kp) * HW_ + 4 * j, true);
        }
        cp_commit();
    };

    stage(0, 0);

    const int lane = tid & 31, warp = tid >> 5;
    const int g = lane >> 2, tq = lane & 3;
    const int cb0 = warp * 32;
    const int afrag = lane * 4;

    float acc[4][4][4];
#pragma unroll
    for (int mt = 0; mt < 4; mt++)
#pragma unroll
        for (int nt = 0; nt < 4; nt++)
#pragma unroll
            for (int q = 0; q < 4; q++) acc[mt][nt][q] = 0.f;

    int buf = 0;
    for (int slab = 0; slab < 4; slab++) {
        cp_wait0();
        __syncthreads();
        if (slab + 1 < 4) stage(slab + 1, buf ^ 1);

        const uint32_t* wa = wsm + buf * ASLAB;
        const uint32_t* bb = bsm + buf * BSLAB;
        uint4 au4[4];
#pragma unroll
        for (int mt = 0; mt < 4; mt++)
            au4[mt] = *(const uint4*)&wa[mt * 128 + afrag];
        int bbase = tq * SKB + cb0 + g;
#pragma unroll
        for (int nt = 0; nt < 4; nt++) {
            uint32_t b0 = bb[bbase + 8 * nt];
            uint32_t b1 = bb[bbase + 4 * SKB + 8 * nt];
#pragma unroll
            for (int mt = 0; mt < 4; mt++)
                mma_f16(acc[mt][nt], (const uint32_t*)&au4[mt], b0, b1);
        }
        buf ^= 1;
    }

#pragma unroll
    for (int mt = 0; mt < 4; mt++) {
        const int oc = oc0 + 16 * mt + g;
        const float bv0 = bias[oc], bv1 = bias[oc + 8];
#pragma unroll
        for (int nt = 0; nt < 4; nt++) {
            const int pc = p0 + cb0 + 8 * nt + 2 * tq;
            int e0 = b * GBS_ + oc * HW_ + pc;
            int e1 = e0 + 8 * HW_;
            *(__half2*)&t[e0] = __floats2half2_rn(acc[mt][nt][0] + bv0, acc[mt][nt][1] + bv0);
            *(__half2*)&t[e1] = __floats2half2_rn(acc[mt][nt][2] + bv1, acc[mt][nt][3] + bv1);
        }
    }
}

// ---------------- depthwise 3x3: half in, half out ----------------
__global__ __launch_bounds__(256)
void dwconv_v3_kernel(const __half* __restrict__ t, const float* __restrict__ w_dw,
                      const float* __restrict__ b_dw, __half* __restrict__ g)
{
    __shared__ float xs[18][136];
    const int tid = threadIdx.x;
    const int s1_0 = blockIdx.x * 16;
    const int og = blockIdx.y, b = blockIdx.z;
    const int base = b * GBS_ + og * HW_;

    if (tid < 36) {
        int row = tid >> 1, side = tid & 1;
        xs[row][side ? 132 : 3] = 0.f;
    }
    for (int idx = tid; idx < 576; idx += 256) {
        int row = idx >> 5, q = idx & 31;
        int s1g = s1_0 - 1 + row;
        float4 v = make_float4(0.f, 0.f, 0.f, 0.f);
        if (s1g >= 0 && s1g < 128)
            v = h4_to_f4(*(const uint2*)&t[base + s1g * 128 + q * 4]);
        xs[row][4 + q * 4 + 0] = v.x;
        xs[row][4 + q * 4 + 1] = v.y;
        xs[row][4 + q * 4 + 2] = v.z;
        xs[row][4 + q * 4 + 3] = v.w;
    }
    __syncthreads();

    float w[9];
#pragma unroll
    for (int k = 0; k < 9; k++) w[k] = w_dw[og * 9 + k];
    float bb = b_dw[og];

    const int r = tid >> 4, cb = (tid & 15) * 8;
    float o[8];
#pragma unroll
    for (int j = 0; j < 8; j++) {
        float s = bb;
#pragma unroll
        for (int dr = 0; dr < 3; dr++)
#pragma unroll
            for (int dc = 0; dc < 3; dc++)
                s += w[dr * 3 + dc] * xs[r + dr][cb + j + 3 + dc];
        o[j] = s;
    }
    __half2 q0 = __floats2half2_rn(o[0], o[1]);
    __half2 q1 = __floats2half2_rn(o[2], o[3]);
    __half2 q2 = __floats2half2_rn(o[4], o[5]);
    __half2 q3 = __floats2half2_rn(o[6], o[7]);
    uint4 u = make_uint4(*(uint32_t*)&q0, *(uint32_t*)&q1, *(uint32_t*)&q2, *(uint32_t*)&q3);
    *(uint4*)&g[base + (s1_0 + r) * 128 + cb] = u;
}

// ---------------- fp16 tensor-core implicit-GEMM 3x3 conv ----------------
// OUTH: 0 fp32 planar (+RES), 1 half2 pair-interleaved (PERM), 2 half planar
template<int C, int S1, int W, int OUTV, int RES, int OUTH>
__global__ __launch_bounds__(256, 2)
void conv3x3_f16(const uint32_t* __restrict__ xh2, const __half* __restrict__ wprep,
                 const float* __restrict__ bias, void* __restrict__ outv,
                 const float* __restrict__ res,
                 int o_oc, int o_s1, int o_s2, int o_b)
{
    constexpr int TR = 256 / W;
    constexpr int NS = C / 16;
    constexpr int RW = W + 8;
    constexpr int SK = (TR + 2) * RW + 8;
    constexpr int ASLAB = 9 * 512;
    constexpr int BSLAB = 8 * SK;
    constexpr int BCH = W / 4;

    extern __shared__ uint32_t smu[];
    uint32_t* wsm = smu;
    uint32_t* bsm = smu + 2 * ASLAB;

    const int tid = threadIdx.x;
    const int s1_0 = blockIdx.x * TR;
    const int oc0 = blockIdx.y * 64;
    const int b = blockIdx.z;
    const uint32_t* xb = xh2 + b * ((C / 2) * S1 * W);
    const __half* wsrc = wprep + blockIdx.y * (NS * 9216);

    for (int i = tid; i < 2 * 8 * (TR + 2) * 2; i += 256) {
        int side = i & 1; int rest = i >> 1;
        int row = rest % (TR + 2); rest /= (TR + 2);
        int kp = rest & 7; int bufi = rest >> 3;
        bsm[bufi * BSLAB + kp * SK + row * RW + (side ? (W + 4) : 3)] = 0u;
    }

    auto stageA = [&](int slab, int bufi) {
        uint32_t d0 = (uint32_t)__cvta_generic_to_shared(wsm + bufi * ASLAB);
        const __half* src = wsrc + slab * 9216;
        for (int i = tid; i < 1152; i += 256)
            cp_async16(d0 + (uint32_t)(i * 16), src + i * 8, true);
    };
    auto stageB = [&](int slab, int bufi) {
        uint32_t d0 = (uint32_t)__cvta_generic_to_shared(bsm + bufi * BSLAB);
        const uint32_t* src = xb + slab * 8 * (S1 * W);
        for (int i = tid; i < 8 * (TR + 2) * BCH; i += 256) {
            int j = i % BCH; int rest = i / BCH;
            int row = rest % (TR + 2); int kp = rest / (TR + 2);
            int s1g = s1_0 - 1 + row;
            bool v = (s1g >= 0) && (s1g < S1);
            int s1c = v ? s1g : 0;
            cp_async16(d0 + (uint32_t)((kp * SK + row * RW + 4 + 4 * j) * 4),
                       src + kp * (S1 * W) + s1c * W + 4 * j, v);
        }
    };

    stageA(0, 0); stageB(0, 0); cp_commit();

    const int lane = tid & 31, warp = tid >> 5;
    const int g = lane >> 2, tq = lane & 3;
    const int rbase = (warp * 32) / W;
    const int cb0 = (warp * 32) % W;
    const int afrag = lane * 4;

    float acc[4][4][4];
#pragma unroll
    for (int mt = 0; mt < 4; mt++)
#pragma unroll
        for (int nt = 0; nt < 4; nt++)
#pragma unroll
            for (int q = 0; q < 4; q++) acc[mt][nt][q] = 0.f;

    int buf = 0;
    for (int slab = 0; slab < NS; slab++) {
        cp_wait0();
        __syncthreads();
        if (slab + 1 < NS) { stageA(slab + 1, buf ^ 1); stageB(slab + 1, buf ^ 1); cp_commit(); }

        const uint32_t* wa = wsm + buf * ASLAB;
        const uint32_t* bb = bsm + buf * BSLAB;
#pragma unroll
        for (int dr = 0; dr < 3; dr++) {
#pragma unroll
            for (int dc = 0; dc < 3; dc++) {
                const int s = dr * 3 + dc;
                uint4 au4[4];
                const uint32_t* wp = &wa[s * 512 + afrag];
#pragma unroll
                for (int mt = 0; mt < 4; mt++)
                    au4[mt] = *(const uint4*)&wp[mt * 128];
                int bbase = tq * SK + (rbase + dr) * RW + cb0 + g + dc + 3;
#pragma unroll
                for (int nt = 0; nt < 4; nt++) {
                    uint32_t b0 = bb[bbase + 8 * nt];
                    uint32_t b1 = bb[bbase + 4 * SK + 8 * nt];
#pragma unroll
                    for (int mt = 0; mt < 4; mt++)
                        mma_f16(acc[mt][nt], (const uint32_t*)&au4[mt], b0, b1);
                }
            }
        }
        buf ^= 1;
    }

    const int s1 = s1_0 + rbase;
    if (OUTH == 1) {
        uint32_t* outp = (uint32_t*)outv;
#pragma unroll
        for (int mt = 0; mt < 4; mt++) {
            const int ocb16 = oc0 + 16 * mt;
            const float bve = bias[ocb16 + 2 * g];
            const float bvo = bias[ocb16 + 2 * g + 1];
            const int ocp = (ocb16 >> 1) + g;
#pragma unroll
            for (int nt = 0; nt < 4; nt++) {
                const int px = cb0 + 8 * nt + 2 * tq;
                float v0 = lrelu(acc[mt][nt][0] + bve);
                float v1 = lrelu(acc[mt][nt][1] + bve);
                float v2 = lrelu(acc[mt][nt][2] + bvo);
                float v3 = lrelu(acc[mt][nt][3] + bvo);
                __half2 h0 = __floats2half2_rn(v0, v2);
                __half2 h1 = __floats2half2_rn(v1, v3);
                int e = b * o_b + ocp * o_oc + s1 * o_s1 + px;
                *(uint2*)&outp[e] = make_uint2(*(uint32_t*)&h0, *(uint32_t*)&h1);
            }
        }
    } else if (OUTH == 2) {
        __half* outh = (__half*)outv;
#pragma unroll
        for (int mt = 0; mt < 4; mt++) {
            const int oc = oc0 + 16 * mt + g;
            const float bv0 = bias[oc], bv1 = bias[oc + 8];
#pragma unroll
            for (int nt = 0; nt < 4; nt++) {
                const int pc = cb0 + 8 * nt + 2 * tq;
                float v0 = lrelu(acc[mt][nt][0] + bv0);
                float v1 = lrelu(acc[mt][nt][1] + bv0);
                float v2 = lrelu(acc[mt][nt][2] + bv1);
                float v3 = lrelu(acc[mt][nt][3] + bv1);
                if (OUTV == 0) {
                    int e0 = b * o_b + oc * o_oc + s1 * o_s1 + pc;
                    int e1 = e0 + 8 * o_oc;
                    *(__half2*)&outh[e0] = __floats2half2_rn(v0, v1);
                    *(__half2*)&outh[e1] = __floats2half2_rn(v2, v3);
                } else {
                    int e = b * o_b + s1 * o_s1 + oc;
                    outh[e + pc * o_s2] = __float2half_rn(v0);
                    outh[e + (pc + 1) * o_s2] = __float2half_rn(v1);
                    outh[e + 8 + pc * o_s2] = __float2half_rn(v2);
                    outh[e + 8 + (pc + 1) * o_s2] = __float2half_rn(v3);
                }
            }
        }
    } else {
        float* out = (float*)outv;
#pragma unroll
        for (int mt = 0; mt < 4; mt++) {
            const int oc = oc0 + 16 * mt + g;
            const float bv0 = bias[oc], bv1 = bias[oc + 8];
#pragma unroll
            for (int nt = 0; nt < 4; nt++) {
                const int pc = cb0 + 8 * nt + 2 * tq;
                float v0 = lrelu(acc[mt][nt][0] + bv0);
                float v1 = lrelu(acc[mt][nt][1] + bv0);
                float v2 = lrelu(acc[mt][nt][2] + bv1);
                float v3 = lrelu(acc[mt][nt][3] + bv1);
                int e0 = b * o_b + oc * o_oc + s1 * o_s1 + pc;
                int e1 = e0 + 8 * o_oc;
                if (RES) {
                    v0 += res[e0]; v1 += res[e0 + 1];
                    v2 += res[e1]; v3 += res[e1 + 1];
                }
                *(float2*)&out[e0] = make_float2(v0, v1);
                *(float2*)&out[e1] = make_float2(v2, v3);
            }
        }
    }
}

// ---------------- down-GEMM ----------------
__global__ __launch_bounds__(256)
void gemm_down_f16(const uint32_t* __restrict__ xr, const __half* __restrict__ g,
                   const __half* __restrict__ xhw, const __half* __restrict__ xcw,
                   const __half* __restrict__ xhc, const __half* __restrict__ wdf,
                   const float* __restrict__ b_down, uint32_t* __restrict__ midh2)
{
    constexpr int SKB = 264;
    __shared__ __align__(16) uint32_t asmem[16 * 512];
    __shared__ __align__(16) uint32_t bsm[2 * 8 * SKB];

    const int tid = threadIdx.x;
    const int p0 = blockIdx.x * 256;
    const int b = blockIdx.z;

    {
        uint32_t dA = (uint32_t)__cvta_generic_to_shared(asmem);
        for (int i = tid; i < 2048; i += 256)
            cp_async16(dA + (uint32_t)(i * 16), wdf + i * 8, true);
        cp_commit();
    }

    const int lane = tid & 31, warp = tid >> 5;
    const int gq = lane >> 2, tq = lane & 3;
    const int cb0 = warp * 32;

    const int kp = tid >> 5;
    const int pxc = (tid & 31) * 8;
    const int pxg = p0 + pxc;

    uint4 r0, r1, r2, r3;

    auto loadRegs = [&](int s) {
        if (s < 4) {
            const uint32_t* src = xr + (b * 32 + s * 8 + kp) * HW_ + pxg;
            r0 = *(const uint4*)src;
            r1 = *(const uint4*)(src + 4);
        } else {
            int s4 = s - 4;
            int gc = 16 * s4 + 2 * kp;
            const __half* gp0 = g + (b * 192 + gc) * HW_ + pxg;
            const __half* br = (s4 < 4) ? xhw : ((s4 < 8) ? xcw : xhc);
            int bc = (s4 & 3) * 16 + 2 * kp;
            const __half* bp0 = br + (b * 64 + bc) * HW_ + pxg;
            r0 = *(const uint4*)gp0;
            r1 = *(const uint4*)(gp0 + HW_);
            r2 = *(const uint4*)bp0;
            r3 = *(const uint4*)(bp0 + HW_);
        }
    };
    auto stsRegs = [&](int s, int bufi) {
        uint32_t* dst = bsm + bufi * (8 * SKB) + kp * SKB + pxc;
        if (s < 4) {
            *(uint4*)dst = r0;
            *(uint4*)(dst + 4) = r1;
        } else {
            const __half* G0 = (const __half*)&r0;
            const __half* G1 = (const __half*)&r1;
            const __half* B0 = (const __half*)&r2;
            const __half* B1 = (const __half*)&r3;
            uint32_t o[8];
#pragma unroll
            for (int j = 0; j < 8; j++) {
                __half2 h = __floats2half2_rn(
                    __half2float(G0[j]) * __half2float(B0[j]),
                    __half2float(G1[j]) * __half2float(B1[j]));
                o[j] = *(uint32_t*)&h;
            }
            *(uint4*)dst = make_uint4(o[0], o[1], o[2], o[3]);
            *(uint4*)(dst + 4) = make_uint4(o[4], o[5], o[6], o[7]);
        }
    };

    float acc[4][4][4];
#pragma unroll
    for (int mt = 0; mt < 4; mt++)
#pragma unroll
        for (int nt = 0; nt < 4; nt++)
#pragma unroll
            for (int q = 0; q < 4; q++) acc[mt][nt][q] = 0.f;

    cp_wait0();
    loadRegs(0);
    stsRegs(0, 0);
    __syncthreads();

    int buf = 0;
    for (int s = 0; s < 16; s++) {
        if (s + 1 < 16) loadRegs(s + 1);
        const uint32_t* wa = asmem + s * 512;
        uint4 au4[4];
#pragma unroll
        for (int mt = 0; mt < 4; mt++)
            au4[mt] = *(const uint4*)&wa[mt * 128 + lane * 4];
        const uint32_t* bb = bsm + buf * (8 * SKB);
        int bbase = tq * SKB + cb0 + gq;
#pragma unroll
        for (int nt = 0; nt < 4; nt++) {
            uint32_t b0 = bb[bbase + 8 * nt];
            uint32_t b1 = bb[bbase + 4 * SKB + 8 * nt];
#pragma unroll
            for (int mt = 0; mt < 4; mt++)
                mma_f16(acc[mt][nt], (const uint32_t*)&au4[mt], b0, b1);
        }
        if (s + 1 < 16) {
            stsRegs(s + 1, buf ^ 1);
            __syncthreads();
        }
        buf ^= 1;
    }

#pragma unroll
    for (int mt = 0; mt < 4; mt++) {
        const float be = b_down[16 * mt + 2 * gq];
        const float bo = b_down[16 * mt + 2 * gq + 1];
        const int ocp = 8 * mt + gq;
#pragma unroll
        for (int nt = 0; nt < 4; nt++) {
            const int pc = p0 + cb0 + 8 * nt + 2 * tq;
            uint2 xres = *(const uint2*)&xr[(b * 32 + ocp) * HW_ + pc];
            float2 xa = __half22float2(*(__half2*)&xres.x);
            float2 xb2 = __half22float2(*(__half2*)&xres.y);
            float v0 = acc[mt][nt][0] + be + xa.x;
            float v2 = acc[mt][nt][2] + bo + xa.y;
            float v1 = acc[mt][nt][1] + be + xb2.x;
            float v3 = acc[mt][nt][3] + bo + xb2.y;
            __half2 m0 = __floats2half2_rn(v0, v2);
            __half2 m1 = __floats2half2_rn(v1, v3);
            *(uint2*)&midh2[(b * 32 + ocp) * HW_ + pc] =
                make_uint2(*(uint32_t*)&m0, *(uint32_t*)&m1);
        }
    }
}

// ---------------- stream/event pool ----------------
struct AsyncCtx {
    cudaStream_t s1, s2, s3;
    cudaEvent_t eRoot, eR4, eCw, eHc, eHw, eT1;
    bool ok;
    AsyncCtx() {
        ok = true;
        ok &= (cudaStreamCreateWithFlags(&s1, cudaStreamNonBlocking) == cudaSuccess);
        ok &= (cudaStreamCreateWithFlags(&s2, cudaStreamNonBlocking) == cudaSuccess);
        ok &= (cudaStreamCreateWithFlags(&s3, cudaStreamNonBlocking) == cudaSuccess);
        ok &= (cudaEventCreateWithFlags(&eRoot, cudaEventDisableTiming) == cudaSuccess);
        ok &= (cudaEventCreateWithFlags(&eR4, cudaEventDisableTiming) == cudaSuccess);
        ok &= (cudaEventCreateWithFlags(&eCw, cudaEventDisableTiming) == cudaSuccess);
        ok &= (cudaEventCreateWithFlags(&eHc, cudaEventDisableTiming) == cudaSuccess);
        ok &= (cudaEventCreateWithFlags(&eHw, cudaEventDisableTiming) == cudaSuccess);
        ok &= (cudaEventCreateWithFlags(&eT1, cudaEventDisableTiming) == cudaSuccess);
    }
};

// ---------------- launch ----------------
extern "C" void kernel_launch(void* const* d_in, const int* in_sizes, int n_in,
                              void* d_out, int out_size)
{
    const float* x      = (const float*)d_in[0];
    const float* w_hwc  = (const float*)d_in[1];
    const float* b_hwc  = (const float*)d_in[2];
    const float* w_dw   = (const float*)d_in[3];
    const float* b_dw   = (const float*)d_in[4];
    const float* w_hw   = (const float*)d_in[5];
    const float* b_hw   = (const float*)d_in[6];
    const float* w_cw   = (const float*)d_in[7];
    const float* b_cw   = (const float*)d_in[8];
    const float* w_hc   = (const float*)d_in[9];
    const float* b_hc   = (const float*)d_in[10];
    const float* w_down = (const float*)d_in[11];
    const float* b_down = (const float*)d_in[12];
    const float* w_l1   = (const float*)d_in[13];
    const float* b_l1   = (const float*)d_in[14];
    const float* w_l2   = (const float*)d_in[15];
    const float* b_l2   = (const float*)d_in[16];
    float* out = (float*)d_out;

    __half *t, *g, *xhw, *xcw, *xhc;
    uint32_t *xt1, *xt2, *xr, *mid, *o1;
    __half *wrh, *w1h, *wdfh;
    { void* p;
      cudaGetSymbolAddress(&p, d_t);   t   = (__half*)p;
      cudaGetSymbolAddress(&p, d_g);   g   = (__half*)p;
      cudaGetSymbolAddress(&p, d_xt1); xt1 = (uint32_t*)p;
      cudaGetSymbolAddress(&p, d_xt2); xt2 = (uint32_t*)p;
      cudaGetSymbolAddress(&p, d_xr);  xr  = (uint32_t*)p;
      cudaGetSymbolAddress(&p, d_xhw); xhw = (__half*)p;
      cudaGetSymbolAddress(&p, d_xcw); xcw = (__half*)p;
      cudaGetSymbolAddress(&p, d_xhc); xhc = (__half*)p;
      cudaGetSymbolAddress(&p, d_mid); mid = (uint32_t*)p;
      cudaGetSymbolAddress(&p, d_o1);  o1  = (uint32_t*)p;
      cudaGetSymbolAddress(&p, d_wr);  wrh = (__half*)p;
      cudaGetSymbolAddress(&p, d_w1);  w1h = (__half*)p;
      cudaGetSymbolAddress(&p, d_wdf); wdfh = (__half*)p;
    }

    __half* wf_hw = wrh;
    __half* wf_cw = wrh + 36864;
    __half* wf_hc = wrh + 184320;
    __half* wf_l1 = wrh + 331776;
    __half* wf_l2 = wrh + 368640;

    const int SM128 = (2 * 4608 + 2 * (8 * ((2 + 2) * 136 + 8))) * 4;  // 72192
    const int SM64  = (2 * 4608 + 2 * (8 * ((4 + 2) * 72 + 8))) * 4;   // 65024

    cudaFuncSetAttribute((const void*)conv3x3_f16<64, 128, 128, 0, 0, 2>,
                         cudaFuncAttributeMaxDynamicSharedMemorySize, SM128);
    cudaFuncSetAttribute((const void*)conv3x3_f16<128, 64, 128, 0, 0, 2>,
                         cudaFuncAttributeMaxDynamicSharedMemorySize, SM128);
    cudaFuncSetAttribute((const void*)conv3x3_f16<128, 128, 64, 1, 0, 2>,
                         cudaFuncAttributeMaxDynamicSharedMemorySize, SM64);
    cudaFuncSetAttribute((const void*)conv3x3_f16<64, 128, 128, 0, 0, 1>,
                         cudaFuncAttributeMaxDynamicSharedMemorySize, SM128);
    cudaFuncSetAttribute((const void*)conv3x3_f16<64, 128, 128, 0, 1, 0>,
                         cudaFuncAttributeMaxDynamicSharedMemorySize, SM128);

    static AsyncCtx ctx;

    // batch-half offsets (elements)
    const int HB = 4;
    const size_t oXR = (size_t)HB * 32 * HW_;   // xr/mid/o1 (u32)
    const size_t oT  = (size_t)HB * GBS_;       // t/g (half)
    const size_t oBR = (size_t)HB * CHW_;       // branches (half) / x,out (float)

    if (ctx.ok) {
        cudaStream_t m = 0;
        cudaEventRecord(ctx.eRoot, m);
        cudaStreamWaitEvent(ctx.s1, ctx.eRoot, 0);
        cudaStreamWaitEvent(ctx.s2, ctx.eRoot, 0);
        cudaStreamWaitEvent(ctx.s3, ctx.eRoot, 0);

        // main: w1 prep + merged xr/xt1 prep
        prep_w1f_kernel<<<48, 256, 0, m>>>(w_hwc, w1h);
        pt1_kernel<<<2048, 256, 0, m>>>(x, xr, xt1);
        cudaEventRecord(ctx.eR4, m);

        // s1: cw branch, then chain-1 gate + tail
        prep_wf_kernel<<<576, 256, 0, ctx.s1>>>(w_cw, wf_cw, 128, 128, 0);
        cudaStreamWaitEvent(ctx.s1, ctx.eR4, 0);
        conv3x3_f16<128, 64, 128, 0, 0, 2><<<dim3(32, 2, 8), 256, SM128, ctx.s1>>>(
            xt1, wf_cw, b_cw, xcw, nullptr, 128, HW_, 1, CHW_);
        cudaEventRecord(ctx.eCw, ctx.s1);

        // s2: hc branch
        prep_wf_kernel<<<576, 256, 0, ctx.s2>>>(w_hc, wf_hc, 128, 128, 0);
        t2f_kernel<<<dim3(4, 2, 1024), dim3(32, 8), 0, ctx.s2>>>(x, xt2);
        conv3x3_f16<128, 128, 64, 1, 0, 2><<<dim3(32, 2, 8), 256, SM64, ctx.s2>>>(
            xt2, wf_hc, b_hc, xhc, nullptr, 1, 128, HW_, CHW_);
        cudaEventRecord(ctx.eHc, ctx.s2);

        // s3: hw branch + misc preps
        prep_wf_kernel<<<144, 256, 0, ctx.s3>>>(w_hw, wf_hw, 64, 64, 0);
        prep_wdf_kernel<<<64, 256, 0, ctx.s3>>>(w_down, wdfh);
        prep_wf_kernel<<<144, 256, 0, ctx.s3>>>(w_l1, wf_l1, 64, 64, 1);
        prep_wf_kernel<<<144, 256, 0, ctx.s3>>>(w_l2, wf_l2, 64, 64, 0);
        cudaStreamWaitEvent(ctx.s3, ctx.eR4, 0);
        conv3x3_f16<64, 128, 128, 0, 0, 2><<<dim3(64, 1, 8), 256, SM128, ctx.s3>>>(
            xr, wf_hw, b_hw, xhw, nullptr, HW_, 128, 1, CHW_);
        cudaEventRecord(ctx.eHw, ctx.s3);

        // ---- chain 0 (b0-3) gate on m ----
        gemm1x1_f16<<<dim3(64, 3, HB), 256, 0, m>>>(xr, w1h, b_hwc, t);
        dwconv_v3_kernel<<<dim3(8, 192, HB), 256, 0, m>>>(t, w_dw, b_dw, g);

        // ---- chain 1 (b4-7) gate on s1 (after cw conv; w1h covered by eR4) ----
        gemm1x1_f16<<<dim3(64, 3, HB), 256, 0, ctx.s1>>>(xr + oXR, w1h, b_hwc, t + oT);
        dwconv_v3_kernel<<<dim3(8, 192, HB), 256, 0, ctx.s1>>>(t + oT, w_dw, b_dw, g + oT);

        // chain 0 joins (cw/hc/hw); gates b0-3 by stream order on m
        cudaStreamWaitEvent(m, ctx.eCw, 0);
        cudaStreamWaitEvent(m, ctx.eHc, 0);
        cudaStreamWaitEvent(m, ctx.eHw, 0);

        // chain 1 joins (cw + gates implicit on s1)
        cudaStreamWaitEvent(ctx.s1, ctx.eHc, 0);
        cudaStreamWaitEvent(ctx.s1, ctx.eHw, 0);

        // chain 0 tail (b0-3) on m
        gemm_down_f16<<<dim3(64, 1, HB), 256, 0, m>>>(xr, g, xhw, xcw, xhc, wdfh, b_down, mid);
        conv3x3_f16<64, 128, 128, 0, 0, 1><<<dim3(64, 1, HB), 256, SM128, m>>>(
            mid, wf_l1, b_l1, o1, nullptr, HW_, 128, 1, 32 * HW_);
        conv3x3_f16<64, 128, 128, 0, 1, 0><<<dim3(64, 1, HB), 256, SM128, m>>>(
            o1, wf_l2, b_l2, out, x, HW_, 128, 1, CHW_);

        // chain 1 tail (b4-7) on s1
        gemm_down_f16<<<dim3(64, 1, HB), 256, 0, ctx.s1>>>(
            xr + oXR, g + oT, xhw + oBR, xcw + oBR, xhc + oBR, wdfh, b_down, mid + oXR);
        conv3x3_f16<64, 128, 128, 0, 0, 1><<<dim3(64, 1, HB), 256, SM128, ctx.s1>>>(
            mid + oXR, wf_l1, b_l1, o1 + oXR, nullptr, HW_, 128, 1, 32 * HW_);
        conv3x3_f16<64, 128, 128, 0, 1, 0><<<dim3(64, 1, HB), 256, SM128, ctx.s1>>>(
            o1 + oXR, wf_l2, b_l2, out + oBR, x + oBR, HW_, 128, 1, CHW_);
        cudaEventRecord(ctx.eT1, ctx.s1);
        cudaStreamWaitEvent(m, ctx.eT1, 0);
    } else {
        // serial fallback
        prep_wf_kernel<<<144, 256>>>(w_hw, wf_hw, 64, 64, 0);
        prep_wf_kernel<<<576, 256>>>(w_cw, wf_cw, 128, 128, 0);
        prep_wf_kernel<<<576, 256>>>(w_hc, wf_hc, 128, 128, 0);
        prep_wf_kernel<<<144, 256>>>(w_l1, wf_l1, 64, 64, 1);
        prep_wf_kernel<<<144, 256>>>(w_l2, wf_l2, 64, 64, 0);
        prep_w1f_kernel<<<48, 256>>>(w_hwc, w1h);
        prep_wdf_kernel<<<64, 256>>>(w_down, wdfh);
        pt1_kernel<<<2048, 256>>>(x, xr, xt1);
        t2f_kernel<<<dim3(4, 2, 1024), dim3(32, 8)>>>(x, xt2);
        gemm1x1_f16<<<dim3(64, 3, 8), 256>>>(xr, w1h, b_hwc, t);
        dwconv_v3_kernel<<<dim3(8, 192, 8), 256>>>(t, w_dw, b_dw, g);
        conv3x3_f16<64, 128, 128, 0, 0, 2><<<dim3(64, 1, 8), 256, SM128>>>(
            xr, wf_hw, b_hw, xhw, nullptr, HW_, 128, 1, CHW_);
        conv3x3_f16<128, 64, 128, 0, 0, 2><<<dim3(32, 2, 8), 256, SM128>>>(
            xt1, wf_cw, b_cw, xcw, nullptr, 128, HW_, 1, CHW_);
        conv3x3_f16<128, 128, 64, 1, 0, 2><<<dim3(32, 2, 8), 256, SM64>>>(
            xt2, wf_hc, b_hc, xhc, nullptr, 1, 128, HW_, CHW_);
        gemm_down_f16<<<dim3(64, 1, 8), 256>>>(xr, g, xhw, xcw, xhc, wdfh, b_down, mid);
        conv3x3_f16<64, 128, 128, 0, 0, 1><<<dim3(64, 1, 8), 256, SM128>>>(
            mid, wf_l1, b_l1, o1, nullptr, HW_, 128, 1, 32 * HW_);
        conv3x3_f16<64, 128, 128, 0, 1, 0><<<dim3(64, 1, 8), 256, SM128>>>(
            o1, wf_l2, b_l2, out, x, HW_, 128, 1, CHW_);
    }
}